// round 5
// baseline (speedup 1.0000x reference)
#include <cuda_runtime.h>
#include <cuda_bf16.h>
#include <math.h>
#include <stdint.h>

#define Bc 8
#define Sc 1024
#define Hc 8
#define Dc 64
#define DMc 512
#define NTOT (Bc*Hc*Sc*Dc)   // 4,194,304

// ---- scratch (device globals; no allocations allowed) ----
__device__ float g_gate[NTOT];   // (B,H,S,D) fp32
__device__ float g_attn[NTOT];   // (B,S,H,D) fp32
__device__ float g_mean[Bc*8];
__device__ float g_rstd[Bc*8];

// bf16 hi/lo attention operands, (B,H,S,D)
__device__ __align__(16) __nv_bfloat16 g_q1h[NTOT], g_q1l[NTOT];
__device__ __align__(16) __nv_bfloat16 g_q2h[NTOT], g_q2l[NTOT];
__device__ __align__(16) __nv_bfloat16 g_k1h[NTOT], g_k1l[NTOT];
__device__ __align__(16) __nv_bfloat16 g_k2h[NTOT], g_k2l[NTOT];
__device__ __align__(16) __nv_bfloat16 g_vh[NTOT],  g_vl[NTOT];

// bf16 hi/lo split operands for tensor-core projection GEMMs
__device__ __align__(16) __nv_bfloat16 g_Ahi[3][8192*512];
__device__ __align__(16) __nv_bfloat16 g_Alo[3][8192*512];
__device__ __align__(16) __nv_bfloat16 g_Whi[3072*512];   // W^T, [N][K] layout
__device__ __align__(16) __nv_bfloat16 g_Wlo[3072*512];

// ============================================================
// helpers
// ============================================================
__device__ __forceinline__ uint32_t smem_u32(const void* p) {
    uint32_t a;
    asm("{ .reg .u64 t; cvta.to.shared.u64 t, %1; cvt.u32.u64 %0, t; }" : "=r"(a) : "l"(p));
    return a;
}
__device__ __forceinline__ void ldsm_x4(uint32_t* r, uint32_t addr) {
    asm volatile("ldmatrix.sync.aligned.m8n8.x4.shared.b16 {%0,%1,%2,%3}, [%4];"
                 : "=r"(r[0]), "=r"(r[1]), "=r"(r[2]), "=r"(r[3]) : "r"(addr));
}
__device__ __forceinline__ void ldsm_x4t(uint32_t* r, uint32_t addr) {
    asm volatile("ldmatrix.sync.aligned.m8n8.x4.trans.shared.b16 {%0,%1,%2,%3}, [%4];"
                 : "=r"(r[0]), "=r"(r[1]), "=r"(r[2]), "=r"(r[3]) : "r"(addr));
}
__device__ __forceinline__ void ldsm_x2(uint32_t* r, uint32_t addr) {
    asm volatile("ldmatrix.sync.aligned.m8n8.x2.shared.b16 {%0,%1}, [%2];"
                 : "=r"(r[0]), "=r"(r[1]) : "r"(addr));
}
__device__ __forceinline__ void mma16816(float* c, const uint32_t* a, const uint32_t* b) {
    asm volatile("mma.sync.aligned.m16n8k16.row.col.f32.bf16.bf16.f32 "
                 "{%0,%1,%2,%3}, {%4,%5,%6,%7}, {%8,%9}, {%0,%1,%2,%3};"
                 : "+f"(c[0]), "+f"(c[1]), "+f"(c[2]), "+f"(c[3])
                 : "r"(a[0]), "r"(a[1]), "r"(a[2]), "r"(a[3]), "r"(b[0]), "r"(b[1]));
}
__device__ __forceinline__ void cp_async16(uint32_t sa, const void* g) {
    asm volatile("cp.async.cg.shared.global [%0], [%1], 16;" :: "r"(sa), "l"(g) : "memory");
}
__device__ __forceinline__ uint32_t packbf(__nv_bfloat16 a, __nv_bfloat16 b) {
    return (uint32_t)__bfloat16_as_ushort(a) | ((uint32_t)__bfloat16_as_ushort(b) << 16);
}
#define SW128(off) ((off) ^ (((off) >> 3) & 0x70))

// ============================================================
// Conversion: fp32 -> bf16 hi + bf16 lo (residual)
// ============================================================
__global__ __launch_bounds__(256)
void convA_kernel(const float* __restrict__ X, int which)
{
    int i = (blockIdx.x * 256 + threadIdx.x) * 4;
    float4 x = *(const float4*)(X + i);
    __nv_bfloat16 h0 = __float2bfloat16(x.x);
    __nv_bfloat16 h1 = __float2bfloat16(x.y);
    __nv_bfloat16 h2 = __float2bfloat16(x.z);
    __nv_bfloat16 h3 = __float2bfloat16(x.w);
    __nv_bfloat16 l0 = __float2bfloat16(x.x - __bfloat162float(h0));
    __nv_bfloat16 l1 = __float2bfloat16(x.y - __bfloat162float(h1));
    __nv_bfloat16 l2 = __float2bfloat16(x.z - __bfloat162float(h2));
    __nv_bfloat16 l3 = __float2bfloat16(x.w - __bfloat162float(h3));
    __nv_bfloat162* ph = (__nv_bfloat162*)(&g_Ahi[which][i]);
    __nv_bfloat162* pl = (__nv_bfloat162*)(&g_Alo[which][i]);
    ph[0] = __nv_bfloat162(h0, h1); ph[1] = __nv_bfloat162(h2, h3);
    pl[0] = __nv_bfloat162(l0, l1); pl[1] = __nv_bfloat162(l2, l3);
}

// Transpose W [K=512][N] -> W^T [N][512] in bf16 hi/lo
__global__ __launch_bounds__(256)
void convW_kernel(const float* __restrict__ W, int N, int off)
{
    __shared__ float t[32][33];
    const int k0 = blockIdx.x * 32;
    const int n0 = blockIdx.y * 32;
    const int tx = threadIdx.x & 31;
    const int ty = threadIdx.x >> 5;
    #pragma unroll
    for (int i = ty; i < 32; i += 8)
        t[i][tx] = W[(size_t)(k0 + i) * N + n0 + tx];
    __syncthreads();
    #pragma unroll
    for (int i = ty; i < 32; i += 8) {
        float x = t[tx][i];
        __nv_bfloat16 h = __float2bfloat16(x);
        size_t idx = (size_t)off + (size_t)(n0 + i) * 512 + k0 + tx;
        g_Whi[idx] = h;
        g_Wlo[idx] = __float2bfloat16(x - __bfloat162float(h));
    }
}

// ============================================================
// HMMA projection GEMM (bf16x3): unchanged from R4 (validated)
// ============================================================
#define AH_OFF 0
#define AL_OFF 16384
#define BH_OFF 32768
#define BL_OFF 49152
#define GEMM_SMEM 65536

__global__ __launch_bounds__(256)
void gemm_hmma(int which, int woff, const float* __restrict__ bias, int perHead, int mode)
{
    extern __shared__ __align__(1024) char smem[];
    const uint32_t sbase = smem_u32(smem);
    const int tid = threadIdx.x;
    const int lane = tid & 31;
    const int wid = tid >> 5;
    const int wm = (wid & 1) * 64;
    const int wn = (wid >> 1) * 32;

    const int m0 = blockIdx.x * 128;
    const int n0 = blockIdx.y * 128;

    const __nv_bfloat16* Ahi = g_Ahi[which];
    const __nv_bfloat16* Alo = g_Alo[which];
    const __nv_bfloat16* Whi = g_Whi + (size_t)woff;
    const __nv_bfloat16* Wlo = g_Wlo + (size_t)woff;

    float C[4][4][4];
    #pragma unroll
    for (int i = 0; i < 4; i++)
        #pragma unroll
        for (int j = 0; j < 4; j++)
            #pragma unroll
            for (int c = 0; c < 4; c++) C[i][j][c] = 0.0f;

    for (int kc = 0; kc < 512; kc += 64) {
        #pragma unroll
        for (int i = 0; i < 4; i++) {
            int idx = tid + 256 * i;
            int row = idx >> 3, u = idx & 7;
            uint32_t soff = SW128((uint32_t)(row * 128 + u * 16));
            *(uint4*)(smem + AH_OFF + soff) = *(const uint4*)(Ahi + (size_t)(m0 + row) * 512 + kc + u * 8);
            *(uint4*)(smem + AL_OFF + soff) = *(const uint4*)(Alo + (size_t)(m0 + row) * 512 + kc + u * 8);
            *(uint4*)(smem + BH_OFF + soff) = *(const uint4*)(Whi + (size_t)(n0 + row) * 512 + kc + u * 8);
            *(uint4*)(smem + BL_OFF + soff) = *(const uint4*)(Wlo + (size_t)(n0 + row) * 512 + kc + u * 8);
        }
        __syncthreads();

        #pragma unroll
        for (int ks = 0; ks < 4; ks++) {
            uint32_t ah[4][4], al[4][4];
            #pragma unroll
            for (int mi = 0; mi < 4; mi++) {
                uint32_t off = (uint32_t)((wm + mi * 16 + (lane & 15)) * 128 + ks * 32 + (lane >> 4) * 16);
                off = SW128(off);
                ldsm_x4(ah[mi], sbase + AH_OFF + off);
                ldsm_x4(al[mi], sbase + AL_OFF + off);
            }
            uint32_t bh[4][2], bl[4][2];
            #pragma unroll
            for (int ni = 0; ni < 4; ni++) {
                uint32_t off = (uint32_t)((wn + ni * 8 + (lane & 7)) * 128 + ks * 32 + ((lane >> 3) & 1) * 16);
                off = SW128(off);
                ldsm_x2(bh[ni], sbase + BH_OFF + off);
                ldsm_x2(bl[ni], sbase + BL_OFF + off);
            }
            #pragma unroll
            for (int mi = 0; mi < 4; mi++)
                #pragma unroll
                for (int ni = 0; ni < 4; ni++) {
                    mma16816(C[mi][ni], ah[mi], bh[ni]);
                    mma16816(C[mi][ni], ah[mi], bl[ni]);
                    mma16816(C[mi][ni], al[mi], bh[ni]);
                }
        }
        __syncthreads();
    }

    #pragma unroll
    for (int ni = 0; ni < 4; ni++) {
        const int ng = n0 + wn + ni * 8 + (lane & 3) * 2;
        const int hh  = ng / perHead;
        const int r   = ng % perHead;
        const int seg = r >> 6;
        const int d   = r & 63;
        const float bx = bias[ng], by = bias[ng + 1];
        __nv_bfloat16 *ph = 0, *pl = 0; float* pf = 0;
        if (mode == 0) {
            if (seg == 0)      { ph = g_q1h; pl = g_q1l; }
            else if (seg == 1) { ph = g_q2h; pl = g_q2l; }
            else               { pf = g_gate; }
        } else if (mode == 1) {
            if (seg == 0) { ph = g_k1h; pl = g_k1l; }
            else          { ph = g_k2h; pl = g_k2l; }
        } else { ph = g_vh; pl = g_vl; }
        #pragma unroll
        for (int mi = 0; mi < 4; mi++) {
            #pragma unroll
            for (int half = 0; half < 2; half++) {
                int m = m0 + wm + mi * 16 + (lane >> 2) + half * 8;
                int bb = m >> 10, s = m & 1023;
                size_t idx = (size_t)((bb * Hc + hh) * Sc + s) * Dc + d;
                float v0 = C[mi][ni][half * 2 + 0] + bx;
                float v1 = C[mi][ni][half * 2 + 1] + by;
                if (pf) {
                    *(float2*)(pf + idx) = make_float2(v0, v1);
                } else {
                    __nv_bfloat16 h0 = __float2bfloat16(v0), h1 = __float2bfloat16(v1);
                    __nv_bfloat16 l0 = __float2bfloat16(v0 - __bfloat162float(h0));
                    __nv_bfloat16 l1 = __float2bfloat16(v1 - __bfloat162float(h1));
                    *(__nv_bfloat162*)(ph + idx) = __nv_bfloat162(h0, h1);
                    *(__nv_bfloat162*)(pl + idx) = __nv_bfloat162(l0, l1);
                }
            }
        }
    }
}

// ============================================================
// HMMA flash attention v2: branch-split warps, full-row
// ownership, register-resident softmax + P fragments.
// warps 0-3: branch1 rows 16w..; warps 4-7: branch2.
// ============================================================
#define AQ1H 0
#define AQ1L 8192
#define AQ2H 16384
#define AQ2L 24576
#define AKV0 32768
#define KVSZ 49152     // per buf: k1h@0 k1l@8192 k2h@16384 k2l@24576 vh@32768 vl@40960
#define ACMB 131072    // 64 x 66 fp32 combine buffer
#define ATTN_SMEM 148480

__global__ __launch_bounds__(256, 1)
void attn_hmma(const float* __restrict__ lam_p)
{
    extern __shared__ __align__(1024) char smem[];
    const uint32_t sb = smem_u32(smem);
    const int tid = threadIdx.x;
    const int lane = tid & 31;
    const int w = tid >> 5;
    const int br = w >> 2;          // 0 = branch1, 1 = branch2
    const int wm = (w & 3) * 16;    // row block

    const int q0 = blockIdx.x * 64;
    const int h = blockIdx.y;
    const int b = blockIdx.z;
    const size_t ho = (size_t)(b * Hc + h) * Sc * Dc;

    const __nv_bfloat16* src[6] = { g_k1h + ho, g_k1l + ho, g_k2h + ho,
                                    g_k2l + ho, g_vh + ho, g_vl + ho };

    // load Q tiles (4 x 64x64 bf16, swizzled)
    {
        const __nv_bfloat16* qs[4] = { g_q1h + ho + (size_t)q0 * Dc, g_q1l + ho + (size_t)q0 * Dc,
                                       g_q2h + ho + (size_t)q0 * Dc, g_q2l + ho + (size_t)q0 * Dc };
        #pragma unroll
        for (int t = 0; t < 4; t++)
            #pragma unroll
            for (int i = 0; i < 2; i++) {
                int idx = tid + 256 * i;
                int row = idx >> 3, u = idx & 7;
                *(uint4*)(smem + t * 8192 + SW128((uint32_t)(row * 128 + u * 16))) =
                    *(const uint4*)(qs[t] + row * 64 + u * 8);
            }
    }
    // prefetch KV tile 0 into buffer 0
    {
        #pragma unroll
        for (int t = 0; t < 6; t++)
            #pragma unroll
            for (int i = 0; i < 2; i++) {
                int idx = tid + 256 * i;
                int row = idx >> 3, u = idx & 7;
                cp_async16(sb + AKV0 + t * 8192 + SW128((uint32_t)(row * 128 + u * 16)),
                           src[t] + (size_t)row * 64 + u * 8);
            }
        asm volatile("cp.async.commit_group;" ::: "memory");
    }

    const uint32_t QH = br ? AQ2H : AQ1H;
    const uint32_t QL = br ? AQ2L : AQ1L;
    const uint32_t KH = br ? 16384u : 0u;
    const uint32_t KL = KH + 8192u;

    float O[8][4];
    #pragma unroll
    for (int nd = 0; nd < 8; nd++)
        #pragma unroll
        for (int c = 0; c < 4; c++) O[nd][c] = 0.0f;
    float m_a = -1e30f, m_b = -1e30f, l_a = 0.0f, l_b = 0.0f;
    const float SC2 = 0.125f * 1.4426950408889634f;   // score scale in log2 domain

    for (int kt = 0; kt < 16; kt++) {
        const uint32_t bufb = AKV0 + (uint32_t)(kt & 1) * KVSZ;
        asm volatile("cp.async.wait_group 0;" ::: "memory");
        __syncthreads();

        // ---- QK^T for this warp's branch (3-term EC) ----
        float s[8][4];
        #pragma unroll
        for (int ni = 0; ni < 8; ni++)
            #pragma unroll
            for (int c = 0; c < 4; c++) s[ni][c] = 0.0f;

        #pragma unroll
        for (int ks = 0; ks < 4; ks++) {
            uint32_t aoff = SW128((uint32_t)((wm + (lane & 15)) * 128 + ks * 32 + ((lane >> 4) << 4)));
            uint32_t ah[4], al[4];
            ldsm_x4(ah, sb + QH + aoff);
            ldsm_x4(al, sb + QL + aoff);
            const uint32_t brow = (uint32_t)((lane & 7) + ((lane >> 4) << 3));
            const uint32_t bcol = (uint32_t)(ks * 32 + (((lane >> 3) & 1) << 4));
            #pragma unroll
            for (int nip = 0; nip < 4; nip++) {
                uint32_t boff = SW128((uint32_t)(nip * 16 + brow) * 128 + bcol);
                uint32_t bh[4], bl[4];
                ldsm_x4(bh, sb + bufb + KH + boff);
                ldsm_x4(bl, sb + bufb + KL + boff);
                mma16816(s[2*nip],   ah, bh);     mma16816(s[2*nip],   ah, bl);     mma16816(s[2*nip],   al, bh);
                mma16816(s[2*nip+1], ah, bh + 2); mma16816(s[2*nip+1], ah, bl + 2); mma16816(s[2*nip+1], al, bh + 2);
            }
        }

        // prefetch next KV tile (overlaps softmax + PV)
        if (kt < 15) {
            const uint32_t nb = AKV0 + (uint32_t)((kt + 1) & 1) * KVSZ;
            #pragma unroll
            for (int t = 0; t < 6; t++)
                #pragma unroll
                for (int i = 0; i < 2; i++) {
                    int idx = tid + 256 * i;
                    int row = idx >> 3, u = idx & 7;
                    cp_async16(sb + nb + t * 8192 + SW128((uint32_t)(row * 128 + u * 16)),
                               src[t] + (size_t)((kt + 1) * 64 + row) * 64 + u * 8);
                }
            asm volatile("cp.async.commit_group;" ::: "memory");
        }

        // ---- register-resident online softmax ----
        float mxa = -1e30f, mxb = -1e30f;
        #pragma unroll
        for (int ni = 0; ni < 8; ni++) {
            s[ni][0] *= SC2; s[ni][1] *= SC2; s[ni][2] *= SC2; s[ni][3] *= SC2;
            mxa = fmaxf(mxa, fmaxf(s[ni][0], s[ni][1]));
            mxb = fmaxf(mxb, fmaxf(s[ni][2], s[ni][3]));
        }
        mxa = fmaxf(mxa, __shfl_xor_sync(0xffffffffu, mxa, 1));
        mxa = fmaxf(mxa, __shfl_xor_sync(0xffffffffu, mxa, 2));
        mxb = fmaxf(mxb, __shfl_xor_sync(0xffffffffu, mxb, 1));
        mxb = fmaxf(mxb, __shfl_xor_sync(0xffffffffu, mxb, 2));
        const float mna = fmaxf(m_a, mxa), mnb = fmaxf(m_b, mxb);
        const float scla = exp2f(m_a - mna), sclb = exp2f(m_b - mnb);

        uint32_t ph[4][4], pl[4][4];
        float suma = 0.0f, sumb = 0.0f;
        #pragma unroll
        for (int ni = 0; ni < 8; ni++) {
            float p0 = exp2f(s[ni][0] - mna);
            float p1 = exp2f(s[ni][1] - mna);
            float p2 = exp2f(s[ni][2] - mnb);
            float p3 = exp2f(s[ni][3] - mnb);
            suma += p0 + p1; sumb += p2 + p3;
            __nv_bfloat16 h0 = __float2bfloat16(p0), h1 = __float2bfloat16(p1);
            __nv_bfloat16 h2 = __float2bfloat16(p2), h3 = __float2bfloat16(p3);
            __nv_bfloat16 e0 = __float2bfloat16(p0 - __bfloat162float(h0));
            __nv_bfloat16 e1 = __float2bfloat16(p1 - __bfloat162float(h1));
            __nv_bfloat16 e2 = __float2bfloat16(p2 - __bfloat162float(h2));
            __nv_bfloat16 e3 = __float2bfloat16(p3 - __bfloat162float(h3));
            const int j = ni >> 1, base = (ni & 1) * 2;
            ph[j][base]     = packbf(h0, h1);
            ph[j][base + 1] = packbf(h2, h3);
            pl[j][base]     = packbf(e0, e1);
            pl[j][base + 1] = packbf(e2, e3);
        }
        suma += __shfl_xor_sync(0xffffffffu, suma, 1);
        suma += __shfl_xor_sync(0xffffffffu, suma, 2);
        sumb += __shfl_xor_sync(0xffffffffu, sumb, 1);
        sumb += __shfl_xor_sync(0xffffffffu, sumb, 2);
        l_a = l_a * scla + suma; l_b = l_b * sclb + sumb;
        m_a = mna; m_b = mnb;
        #pragma unroll
        for (int nd = 0; nd < 8; nd++) {
            O[nd][0] *= scla; O[nd][1] *= scla;
            O[nd][2] *= sclb; O[nd][3] *= sclb;
        }

        // ---- O += P V (3-term EC) ----
        #pragma unroll
        for (int j = 0; j < 4; j++) {
            const uint32_t vrow = (uint32_t)(j * 16 + (lane & 7) + (((lane >> 3) & 1) << 3));
            #pragma unroll
            for (int ndp = 0; ndp < 4; ndp++) {
                uint32_t voff = SW128(vrow * 128 + (uint32_t)(ndp * 32 + ((lane >> 4) << 4)));
                uint32_t vh4[4], vl4[4];
                ldsm_x4t(vh4, sb + bufb + 32768u + voff);
                ldsm_x4t(vl4, sb + bufb + 40960u + voff);
                mma16816(O[2*ndp],   ph[j], vh4);     mma16816(O[2*ndp],   ph[j], vl4);     mma16816(O[2*ndp],   pl[j], vh4);
                mma16816(O[2*ndp+1], ph[j], vh4 + 2); mma16816(O[2*ndp+1], ph[j], vl4 + 2); mma16816(O[2*ndp+1], pl[j], vh4 + 2);
            }
        }
    }

    // ---- combine branches: O = O1/l1 - lam*O2/l2 ----
    float* comb = (float*)(smem + ACMB);   // [64][66]
    const float lam = lam_p[0];
    const int r0 = wm + (lane >> 2);
    __syncthreads();
    if (br == 1) {
        const float ia = lam / l_a, ib = lam / l_b;
        #pragma unroll
        for (int nd = 0; nd < 8; nd++) {
            int c = nd * 8 + (lane & 3) * 2;
            *(float2*)(comb + r0 * 66 + c)       = make_float2(O[nd][0] * ia, O[nd][1] * ia);
            *(float2*)(comb + (r0 + 8) * 66 + c) = make_float2(O[nd][2] * ib, O[nd][3] * ib);
        }
    }
    __syncthreads();
    if (br == 0) {
        const float ia = 1.0f / l_a, ib = 1.0f / l_b;
        #pragma unroll
        for (int nd = 0; nd < 8; nd++) {
            int c = nd * 8 + (lane & 3) * 2;
            float2 g0 = *(float2*)(comb + r0 * 66 + c);
            float2 g1 = *(float2*)(comb + (r0 + 8) * 66 + c);
            float2 v0 = make_float2(O[nd][0] * ia - g0.x, O[nd][1] * ia - g0.y);
            float2 v1 = make_float2(O[nd][2] * ib - g1.x, O[nd][3] * ib - g1.y);
            int s0 = q0 + r0, s1r = s0 + 8;
            *(float2*)(g_attn + (size_t)((b * Sc + s0)  * Hc + h) * Dc + c) = v0;
            *(float2*)(g_attn + (size_t)((b * Sc + s1r) * Hc + h) * Dc + c) = v1;
        }
    }
}

// ============================================================
// Group statistics (unchanged)
// ============================================================
__global__ __launch_bounds__(256)
void stats_kernel()
{
    const int b = blockIdx.x >> 3;
    const int j = blockIdx.x & 7;
    const int tid = threadIdx.x;
    double s = 0.0, sq = 0.0;
    const float* base = g_attn + (size_t)b*Sc*Hc*Dc + j*8;
    for (int t = tid; t < Sc*Hc; t += 256) {
        const float* p = base + (size_t)t * 64;
        #pragma unroll
        for (int i = 0; i < 8; i++) {
            float x = p[i];
            s  += (double)x;
            sq += (double)x * (double)x;
        }
    }
    __shared__ double ss[256], sqq[256];
    ss[tid] = s; sqq[tid] = sq;
    __syncthreads();
    for (int o = 128; o > 0; o >>= 1) {
        if (tid < o) { ss[tid] += ss[tid+o]; sqq[tid] += sqq[tid+o]; }
        __syncthreads();
    }
    if (tid == 0) {
        double mean = ss[0] / 65536.0;
        double var  = sqq[0] / 65536.0 - mean * mean;
        g_mean[blockIdx.x] = (float)mean;
        g_rstd[blockIdx.x] = (float)(1.0 / sqrt(var + 1e-3));
    }
}

// ============================================================
// Final elementwise (unchanged)
// ============================================================
__global__ __launch_bounds__(256)
void final_kernel(const float* __restrict__ gamma, const float* __restrict__ beta,
                  const float* __restrict__ li_p, float* __restrict__ out)
{
    const int idx = (blockIdx.x * 256 + threadIdx.x) * 4;
    const int d = idx & 63;
    const int h = (idx >> 6) & 7;
    const int s = (idx >> 9) & 1023;
    const int b = idx >> 19;
    const int j = d >> 3;
    const float mean = g_mean[b*8+j];
    const float rstd = g_rstd[b*8+j];
    const float li = 1.0f - li_p[0];
    float4 a  = *(const float4*)(g_attn + idx);
    float4 g  = *(const float4*)(g_gate + (size_t)((b*Hc+h)*Sc + s)*Dc + d);
    float4 gm = *(const float4*)(gamma + d);
    float4 bt = *(const float4*)(beta + d);
    float4 o;
    o.x = ((a.x-mean)*rstd*gm.x + bt.x) * li * (1.0f/(1.0f+__expf(-g.x)));
    o.y = ((a.y-mean)*rstd*gm.y + bt.y) * li * (1.0f/(1.0f+__expf(-g.y)));
    o.z = ((a.z-mean)*rstd*gm.z + bt.z) * li * (1.0f/(1.0f+__expf(-g.z)));
    o.w = ((a.w-mean)*rstd*gm.w + bt.w) * li * (1.0f/(1.0f+__expf(-g.w)));
    *(float4*)(out + idx) = o;
}

// ============================================================
extern "C" void kernel_launch(void* const* d_in, const int* in_sizes, int n_in,
                              void* d_out, int out_size)
{
    const float* query  = (const float*)d_in[0];
    const float* key    = (const float*)d_in[1];
    const float* values = (const float*)d_in[2];
    const float* Wq = (const float*)d_in[3];
    const float* bq = (const float*)d_in[4];
    const float* Wk = (const float*)d_in[5];
    const float* bk = (const float*)d_in[6];
    const float* Wv = (const float*)d_in[7];
    const float* bv = (const float*)d_in[8];
    const float* gamma = (const float*)d_in[9];
    const float* beta  = (const float*)d_in[10];
    const float* lam   = (const float*)d_in[11];
    const float* lambda_init = (const float*)d_in[12];
    float* out = (float*)d_out;

    cudaFuncSetAttribute(gemm_hmma, cudaFuncAttributeMaxDynamicSharedMemorySize, GEMM_SMEM);
    cudaFuncSetAttribute(attn_hmma, cudaFuncAttributeMaxDynamicSharedMemorySize, ATTN_SMEM);

    // bf16 hi/lo conversions
    convA_kernel<<<4096, 256>>>(query,  0);
    convA_kernel<<<4096, 256>>>(key,    1);
    convA_kernel<<<4096, 256>>>(values, 2);
    convW_kernel<<<dim3(16, 48), 256>>>(Wq, 1536, 0);
    convW_kernel<<<dim3(16, 32), 256>>>(Wk, 1024, 1536*512);
    convW_kernel<<<dim3(16, 16), 256>>>(Wv,  512, 2560*512);

    // HMMA projection GEMMs
    gemm_hmma<<<dim3(64, 12), 256, GEMM_SMEM>>>(0, 0,        bq, 192, 0);
    gemm_hmma<<<dim3(64,  8), 256, GEMM_SMEM>>>(1, 1536*512, bk, 128, 1);
    gemm_hmma<<<dim3(64,  4), 256, GEMM_SMEM>>>(2, 2560*512, bv,  64, 2);

    // HMMA flash attention v2
    attn_hmma<<<dim3(16, 8, 8), 256, ATTN_SMEM>>>(lam);

    stats_kernel<<<64, 256>>>();
    final_kernel<<<NTOT/1024, 256>>>(gamma, beta, lambda_init, out);
}

// round 6
// speedup vs baseline: 1.1771x; 1.1771x over previous
#include <cuda_runtime.h>
#include <cuda_bf16.h>
#include <math.h>
#include <stdint.h>

#define Bc 8
#define Sc 1024
#define Hc 8
#define Dc 64
#define DMc 512
#define NTOT (Bc*Hc*Sc*Dc)   // 4,194,304

// ---- scratch (device globals; no allocations allowed) ----
__device__ float g_gate[NTOT];   // (B,H,S,D) fp32
__device__ float g_attn[NTOT];   // (B,S,H,D) fp32
__device__ float g_mean[Bc*8];
__device__ float g_rstd[Bc*8];

// bf16 hi/lo attention operands, (B,H,S,D)
__device__ __align__(16) __nv_bfloat16 g_q1h[NTOT], g_q1l[NTOT];
__device__ __align__(16) __nv_bfloat16 g_q2h[NTOT], g_q2l[NTOT];
__device__ __align__(16) __nv_bfloat16 g_k1h[NTOT], g_k1l[NTOT];
__device__ __align__(16) __nv_bfloat16 g_k2h[NTOT], g_k2l[NTOT];
__device__ __align__(16) __nv_bfloat16 g_vh[NTOT],  g_vl[NTOT];

// bf16 hi/lo split operands for tensor-core projection GEMMs
__device__ __align__(16) __nv_bfloat16 g_Ahi[3][8192*512];
__device__ __align__(16) __nv_bfloat16 g_Alo[3][8192*512];
__device__ __align__(16) __nv_bfloat16 g_Whi[3072*512];   // W^T, [N][K] layout
__device__ __align__(16) __nv_bfloat16 g_Wlo[3072*512];

// ============================================================
// helpers
// ============================================================
__device__ __forceinline__ uint32_t smem_u32(const void* p) {
    uint32_t a;
    asm("{ .reg .u64 t; cvta.to.shared.u64 t, %1; cvt.u32.u64 %0, t; }" : "=r"(a) : "l"(p));
    return a;
}
__device__ __forceinline__ void ldsm_x4(uint32_t* r, uint32_t addr) {
    asm volatile("ldmatrix.sync.aligned.m8n8.x4.shared.b16 {%0,%1,%2,%3}, [%4];"
                 : "=r"(r[0]), "=r"(r[1]), "=r"(r[2]), "=r"(r[3]) : "r"(addr));
}
__device__ __forceinline__ void ldsm_x2(uint32_t* r, uint32_t addr) {
    asm volatile("ldmatrix.sync.aligned.m8n8.x2.shared.b16 {%0,%1}, [%2];"
                 : "=r"(r[0]), "=r"(r[1]) : "r"(addr));
}
__device__ __forceinline__ void ldsm_x2t(uint32_t* r, uint32_t addr) {
    asm volatile("ldmatrix.sync.aligned.m8n8.x2.trans.shared.b16 {%0,%1}, [%2];"
                 : "=r"(r[0]), "=r"(r[1]) : "r"(addr));
}
__device__ __forceinline__ void mma16816(float* c, const uint32_t* a, const uint32_t* b) {
    asm volatile("mma.sync.aligned.m16n8k16.row.col.f32.bf16.bf16.f32 "
                 "{%0,%1,%2,%3}, {%4,%5,%6,%7}, {%8,%9}, {%0,%1,%2,%3};"
                 : "+f"(c[0]), "+f"(c[1]), "+f"(c[2]), "+f"(c[3])
                 : "r"(a[0]), "r"(a[1]), "r"(a[2]), "r"(a[3]), "r"(b[0]), "r"(b[1]));
}
__device__ __forceinline__ void cp_async16(uint32_t sa, const void* g) {
    asm volatile("cp.async.cg.shared.global [%0], [%1], 16;" :: "r"(sa), "l"(g) : "memory");
}
#define SW128(off) ((off) ^ (((off) >> 3) & 0x70))

// ============================================================
// Conversion: fp32 -> bf16 hi + bf16 lo (residual)
// ============================================================
__global__ __launch_bounds__(256)
void convA_kernel(const float* __restrict__ X, int which)
{
    int i = (blockIdx.x * 256 + threadIdx.x) * 4;
    float4 x = *(const float4*)(X + i);
    __nv_bfloat16 h0 = __float2bfloat16(x.x);
    __nv_bfloat16 h1 = __float2bfloat16(x.y);
    __nv_bfloat16 h2 = __float2bfloat16(x.z);
    __nv_bfloat16 h3 = __float2bfloat16(x.w);
    __nv_bfloat16 l0 = __float2bfloat16(x.x - __bfloat162float(h0));
    __nv_bfloat16 l1 = __float2bfloat16(x.y - __bfloat162float(h1));
    __nv_bfloat16 l2 = __float2bfloat16(x.z - __bfloat162float(h2));
    __nv_bfloat16 l3 = __float2bfloat16(x.w - __bfloat162float(h3));
    __nv_bfloat162* ph = (__nv_bfloat162*)(&g_Ahi[which][i]);
    __nv_bfloat162* pl = (__nv_bfloat162*)(&g_Alo[which][i]);
    ph[0] = __nv_bfloat162(h0, h1); ph[1] = __nv_bfloat162(h2, h3);
    pl[0] = __nv_bfloat162(l0, l1); pl[1] = __nv_bfloat162(l2, l3);
}

// Transpose W [K=512][N] -> W^T [N][512] in bf16 hi/lo
__global__ __launch_bounds__(256)
void convW_kernel(const float* __restrict__ W, int N, int off)
{
    __shared__ float t[32][33];
    const int k0 = blockIdx.x * 32;
    const int n0 = blockIdx.y * 32;
    const int tx = threadIdx.x & 31;
    const int ty = threadIdx.x >> 5;
    #pragma unroll
    for (int i = ty; i < 32; i += 8)
        t[i][tx] = W[(size_t)(k0 + i) * N + n0 + tx];
    __syncthreads();
    #pragma unroll
    for (int i = ty; i < 32; i += 8) {
        float x = t[tx][i];
        __nv_bfloat16 h = __float2bfloat16(x);
        size_t idx = (size_t)off + (size_t)(n0 + i) * 512 + k0 + tx;
        g_Whi[idx] = h;
        g_Wlo[idx] = __float2bfloat16(x - __bfloat162float(h));
    }
}

// ============================================================
// HMMA projection GEMM (bf16x3): unchanged (validated, 287 TF/s)
// ============================================================
#define AH_OFF 0
#define AL_OFF 16384
#define BH_OFF 32768
#define BL_OFF 49152
#define GEMM_SMEM 65536

__global__ __launch_bounds__(256)
void gemm_hmma(int which, int woff, const float* __restrict__ bias, int perHead, int mode)
{
    extern __shared__ __align__(1024) char smem[];
    const uint32_t sbase = smem_u32(smem);
    const int tid = threadIdx.x;
    const int lane = tid & 31;
    const int wid = tid >> 5;
    const int wm = (wid & 1) * 64;
    const int wn = (wid >> 1) * 32;

    const int m0 = blockIdx.x * 128;
    const int n0 = blockIdx.y * 128;

    const __nv_bfloat16* Ahi = g_Ahi[which];
    const __nv_bfloat16* Alo = g_Alo[which];
    const __nv_bfloat16* Whi = g_Whi + (size_t)woff;
    const __nv_bfloat16* Wlo = g_Wlo + (size_t)woff;

    float C[4][4][4];
    #pragma unroll
    for (int i = 0; i < 4; i++)
        #pragma unroll
        for (int j = 0; j < 4; j++)
            #pragma unroll
            for (int c = 0; c < 4; c++) C[i][j][c] = 0.0f;

    for (int kc = 0; kc < 512; kc += 64) {
        #pragma unroll
        for (int i = 0; i < 4; i++) {
            int idx = tid + 256 * i;
            int row = idx >> 3, u = idx & 7;
            uint32_t soff = SW128((uint32_t)(row * 128 + u * 16));
            *(uint4*)(smem + AH_OFF + soff) = *(const uint4*)(Ahi + (size_t)(m0 + row) * 512 + kc + u * 8);
            *(uint4*)(smem + AL_OFF + soff) = *(const uint4*)(Alo + (size_t)(m0 + row) * 512 + kc + u * 8);
            *(uint4*)(smem + BH_OFF + soff) = *(const uint4*)(Whi + (size_t)(n0 + row) * 512 + kc + u * 8);
            *(uint4*)(smem + BL_OFF + soff) = *(const uint4*)(Wlo + (size_t)(n0 + row) * 512 + kc + u * 8);
        }
        __syncthreads();

        #pragma unroll
        for (int ks = 0; ks < 4; ks++) {
            uint32_t ah[4][4], al[4][4];
            #pragma unroll
            for (int mi = 0; mi < 4; mi++) {
                uint32_t off = (uint32_t)((wm + mi * 16 + (lane & 15)) * 128 + ks * 32 + (lane >> 4) * 16);
                off = SW128(off);
                ldsm_x4(ah[mi], sbase + AH_OFF + off);
                ldsm_x4(al[mi], sbase + AL_OFF + off);
            }
            uint32_t bh[4][2], bl[4][2];
            #pragma unroll
            for (int ni = 0; ni < 4; ni++) {
                uint32_t off = (uint32_t)((wn + ni * 8 + (lane & 7)) * 128 + ks * 32 + ((lane >> 3) & 1) * 16);
                off = SW128(off);
                ldsm_x2(bh[ni], sbase + BH_OFF + off);
                ldsm_x2(bl[ni], sbase + BL_OFF + off);
            }
            #pragma unroll
            for (int mi = 0; mi < 4; mi++)
                #pragma unroll
                for (int ni = 0; ni < 4; ni++) {
                    mma16816(C[mi][ni], ah[mi], bh[ni]);
                    mma16816(C[mi][ni], ah[mi], bl[ni]);
                    mma16816(C[mi][ni], al[mi], bh[ni]);
                }
        }
        __syncthreads();
    }

    #pragma unroll
    for (int ni = 0; ni < 4; ni++) {
        const int ng = n0 + wn + ni * 8 + (lane & 3) * 2;
        const int hh  = ng / perHead;
        const int r   = ng % perHead;
        const int seg = r >> 6;
        const int d   = r & 63;
        const float bx = bias[ng], by = bias[ng + 1];
        __nv_bfloat16 *ph = 0, *pl = 0; float* pf = 0;
        if (mode == 0) {
            if (seg == 0)      { ph = g_q1h; pl = g_q1l; }
            else if (seg == 1) { ph = g_q2h; pl = g_q2l; }
            else               { pf = g_gate; }
        } else if (mode == 1) {
            if (seg == 0) { ph = g_k1h; pl = g_k1l; }
            else          { ph = g_k2h; pl = g_k2l; }
        } else { ph = g_vh; pl = g_vl; }
        #pragma unroll
        for (int mi = 0; mi < 4; mi++) {
            #pragma unroll
            for (int half = 0; half < 2; half++) {
                int m = m0 + wm + mi * 16 + (lane >> 2) + half * 8;
                int bb = m >> 10, s = m & 1023;
                size_t idx = (size_t)((bb * Hc + hh) * Sc + s) * Dc + d;
                float v0 = C[mi][ni][half * 2 + 0] + bx;
                float v1 = C[mi][ni][half * 2 + 1] + by;
                if (pf) {
                    *(float2*)(pf + idx) = make_float2(v0, v1);
                } else {
                    __nv_bfloat16 h0 = __float2bfloat16(v0), h1 = __float2bfloat16(v1);
                    __nv_bfloat16 l0 = __float2bfloat16(v0 - __bfloat162float(h0));
                    __nv_bfloat16 l1 = __float2bfloat16(v1 - __bfloat162float(h1));
                    *(__nv_bfloat162*)(ph + idx) = __nv_bfloat162(h0, h1);
                    *(__nv_bfloat162*)(pl + idx) = __nv_bfloat162(l0, l1);
                }
            }
        }
    }
}

// ============================================================
// HMMA flash attention (R4 structure, 512 threads / 16 warps):
// warp grid 4m x 4n; each warp 16 rows x 16 cols, BOTH branches.
// Two online softmaxes in smem; exp2f log2-domain.
// ============================================================
#define AQ1H 0
#define AQ1L 8192
#define AQ2H 16384
#define AQ2L 24576
#define AKV0 32768
#define KVSZ 49152     // per buf: k1h@0 k1l@8192 k2h@16384 k2l@24576 vh@32768 vl@40960
#define AP1H 131072
#define AP1L 139264
#define AP2H 147456
#define AP2L 155648
#define AS1  163840
#define AS2  180480
#define ASTAT 197120
#define ATTN_SMEM 198656

__global__ __launch_bounds__(512, 1)
void attn_hmma(const float* __restrict__ lam_p)
{
    extern __shared__ __align__(1024) char smem[];
    const uint32_t sb = smem_u32(smem);
    const int tid = threadIdx.x;
    const int lane = tid & 31;
    const int w = tid >> 5;
    const int wm = (w & 3) * 16;      // 4 row blocks
    const int wn = (w >> 2) * 16;     // 4 col blocks of 16

    const int q0 = blockIdx.x * 64;
    const int h = blockIdx.y;
    const int b = blockIdx.z;
    const size_t ho = (size_t)(b * Hc + h) * Sc * Dc;

    const __nv_bfloat16* src[6] = { g_k1h + ho, g_k1l + ho, g_k2h + ho,
                                    g_k2l + ho, g_vh + ho, g_vl + ho };

    float* stm1 = (float*)(smem + ASTAT);
    float* stl1 = stm1 + 64;
    float* stm2 = stl1 + 64;
    float* stl2 = stm2 + 64;
    float* stsc1 = stl2 + 64;
    float* stsc2 = stsc1 + 64;

    // load Q tiles (4 x 64x64 bf16, swizzled): 512 chunks per tile
    {
        const __nv_bfloat16* qs[4] = { g_q1h + ho + (size_t)q0 * Dc, g_q1l + ho + (size_t)q0 * Dc,
                                       g_q2h + ho + (size_t)q0 * Dc, g_q2l + ho + (size_t)q0 * Dc };
        #pragma unroll
        for (int t = 0; t < 4; t++) {
            int row = tid >> 3, u = tid & 7;
            *(uint4*)(smem + t * 8192 + SW128((uint32_t)(row * 128 + u * 16))) =
                *(const uint4*)(qs[t] + row * 64 + u * 8);
        }
    }
    if (tid < 64) {
        stm1[tid] = -1e30f; stl1[tid] = 0.0f;
        stm2[tid] = -1e30f; stl2[tid] = 0.0f;
    }

    // prologue: KV tile 0 into buffer 0
    {
        int row = tid >> 3, u = tid & 7;
        uint32_t soff = SW128((uint32_t)(row * 128 + u * 16));
        #pragma unroll
        for (int t = 0; t < 6; t++)
            cp_async16(sb + AKV0 + t * 8192 + soff, src[t] + (size_t)row * 64 + u * 8);
        asm volatile("cp.async.commit_group;" ::: "memory");
    }

    float O1[2][4], O2[2][4];
    #pragma unroll
    for (int ni = 0; ni < 2; ni++)
        #pragma unroll
        for (int c = 0; c < 4; c++) { O1[ni][c] = 0.0f; O2[ni][c] = 0.0f; }

    float* S1F = (float*)(smem + AS1);
    float* S2F = (float*)(smem + AS2);
    const float SC2 = 0.125f * 1.4426950408889634f;   // fold /8 and log2e

    for (int kt = 0; kt < 16; kt++) {
        const uint32_t bufb = AKV0 + (uint32_t)(kt & 1) * KVSZ;
        asm volatile("cp.async.wait_group 0;" ::: "memory");
        __syncthreads();

        // ---- QK^T (both branches, 3-term EC) ----
        float s1[2][4], s2[2][4];
        #pragma unroll
        for (int ni = 0; ni < 2; ni++)
            #pragma unroll
            for (int c = 0; c < 4; c++) { s1[ni][c] = 0.0f; s2[ni][c] = 0.0f; }

        #pragma unroll
        for (int ks = 0; ks < 4; ks++) {
            uint32_t aoff = SW128((uint32_t)((wm + (lane & 15)) * 128 + ks * 32 + (lane >> 4) * 16));
            uint32_t a1h[4], a1l[4], a2h[4], a2l[4];
            ldsm_x4(a1h, sb + AQ1H + aoff); ldsm_x4(a1l, sb + AQ1L + aoff);
            ldsm_x4(a2h, sb + AQ2H + aoff); ldsm_x4(a2l, sb + AQ2L + aoff);
            #pragma unroll
            for (int ni = 0; ni < 2; ni++) {
                uint32_t boff = SW128((uint32_t)((wn + ni * 8 + (lane & 7)) * 128 + ks * 32 + ((lane >> 3) & 1) * 16));
                uint32_t b1h[2], b1l[2], b2h[2], b2l[2];
                ldsm_x2(b1h, sb + bufb + 0     + boff);
                ldsm_x2(b1l, sb + bufb + 8192  + boff);
                ldsm_x2(b2h, sb + bufb + 16384 + boff);
                ldsm_x2(b2l, sb + bufb + 24576 + boff);
                mma16816(s1[ni], a1h, b1h); mma16816(s1[ni], a1h, b1l); mma16816(s1[ni], a1l, b1h);
                mma16816(s2[ni], a2h, b2h); mma16816(s2[ni], a2h, b2l); mma16816(s2[ni], a2l, b2h);
            }
        }
        {
            int r0 = wm + (lane >> 2), r1 = r0 + 8;
            #pragma unroll
            for (int ni = 0; ni < 2; ni++) {
                int cc = wn + ni * 8 + (lane & 3) * 2;
                S1F[r0 * 65 + cc]     = s1[ni][0] * SC2;
                S1F[r0 * 65 + cc + 1] = s1[ni][1] * SC2;
                S1F[r1 * 65 + cc]     = s1[ni][2] * SC2;
                S1F[r1 * 65 + cc + 1] = s1[ni][3] * SC2;
                S2F[r0 * 65 + cc]     = s2[ni][0] * SC2;
                S2F[r0 * 65 + cc + 1] = s2[ni][1] * SC2;
                S2F[r1 * 65 + cc]     = s2[ni][2] * SC2;
                S2F[r1 * 65 + cc + 1] = s2[ni][3] * SC2;
            }
        }

        // prefetch next KV tile (overlaps softmax + PV)
        if (kt < 15) {
            const uint32_t nb = AKV0 + (uint32_t)((kt + 1) & 1) * KVSZ;
            int row = tid >> 3, u = tid & 7;
            uint32_t soff = SW128((uint32_t)(row * 128 + u * 16));
            #pragma unroll
            for (int t = 0; t < 6; t++)
                cp_async16(sb + nb + t * 8192 + soff,
                           src[t] + (size_t)((kt + 1) * 64 + row) * 64 + u * 8);
            asm volatile("cp.async.commit_group;" ::: "memory");
        }
        __syncthreads();

        // ---- online softmax (log2 domain), write P bf16 hi/lo ----
        {
            const int row = tid >> 3;          // 0..63
            const int base = (tid & 7) * 8;    // 8 cols per thread

            // branch 1
            float mx = -1e30f;
            #pragma unroll
            for (int c = 0; c < 8; c++) mx = fmaxf(mx, S1F[row * 65 + base + c]);
            mx = fmaxf(mx, __shfl_xor_sync(0xffffffffu, mx, 1));
            mx = fmaxf(mx, __shfl_xor_sync(0xffffffffu, mx, 2));
            mx = fmaxf(mx, __shfl_xor_sync(0xffffffffu, mx, 4));
            float mold = stm1[row];
            float mnew = fmaxf(mold, mx);
            float sum = 0.0f;
            #pragma unroll
            for (int c = 0; c < 8; c += 2) {
                float p0 = exp2f(S1F[row * 65 + base + c]     - mnew);
                float p1 = exp2f(S1F[row * 65 + base + c + 1] - mnew);
                sum += p0 + p1;
                __nv_bfloat16 h0 = __float2bfloat16(p0), h1 = __float2bfloat16(p1);
                __nv_bfloat16 l0 = __float2bfloat16(p0 - __bfloat162float(h0));
                __nv_bfloat16 l1 = __float2bfloat16(p1 - __bfloat162float(h1));
                uint32_t off = SW128((uint32_t)(row * 128 + (base + c) * 2));
                *(__nv_bfloat162*)(smem + AP1H + off) = __nv_bfloat162(h0, h1);
                *(__nv_bfloat162*)(smem + AP1L + off) = __nv_bfloat162(l0, l1);
            }
            sum += __shfl_xor_sync(0xffffffffu, sum, 1);
            sum += __shfl_xor_sync(0xffffffffu, sum, 2);
            sum += __shfl_xor_sync(0xffffffffu, sum, 4);
            if ((tid & 7) == 0) {
                float scl = exp2f(mold - mnew);
                stsc1[row] = scl;
                stl1[row] = stl1[row] * scl + sum;
                stm1[row] = mnew;
            }

            // branch 2
            mx = -1e30f;
            #pragma unroll
            for (int c = 0; c < 8; c++) mx = fmaxf(mx, S2F[row * 65 + base + c]);
            mx = fmaxf(mx, __shfl_xor_sync(0xffffffffu, mx, 1));
            mx = fmaxf(mx, __shfl_xor_sync(0xffffffffu, mx, 2));
            mx = fmaxf(mx, __shfl_xor_sync(0xffffffffu, mx, 4));
            mold = stm2[row];
            mnew = fmaxf(mold, mx);
            sum = 0.0f;
            #pragma unroll
            for (int c = 0; c < 8; c += 2) {
                float p0 = exp2f(S2F[row * 65 + base + c]     - mnew);
                float p1 = exp2f(S2F[row * 65 + base + c + 1] - mnew);
                sum += p0 + p1;
                __nv_bfloat16 h0 = __float2bfloat16(p0), h1 = __float2bfloat16(p1);
                __nv_bfloat16 l0 = __float2bfloat16(p0 - __bfloat162float(h0));
                __nv_bfloat16 l1 = __float2bfloat16(p1 - __bfloat162float(h1));
                uint32_t off = SW128((uint32_t)(row * 128 + (base + c) * 2));
                *(__nv_bfloat162*)(smem + AP2H + off) = __nv_bfloat162(h0, h1);
                *(__nv_bfloat162*)(smem + AP2L + off) = __nv_bfloat162(l0, l1);
            }
            sum += __shfl_xor_sync(0xffffffffu, sum, 1);
            sum += __shfl_xor_sync(0xffffffffu, sum, 2);
            sum += __shfl_xor_sync(0xffffffffu, sum, 4);
            if ((tid & 7) == 0) {
                float scl = exp2f(mold - mnew);
                stsc2[row] = scl;
                stl2[row] = stl2[row] * scl + sum;
                stm2[row] = mnew;
            }
        }
        __syncthreads();

        // ---- rescale O, then O += P V ----
        {
            float fa1 = stsc1[wm + (lane >> 2)], fb1 = stsc1[wm + (lane >> 2) + 8];
            float fa2 = stsc2[wm + (lane >> 2)], fb2 = stsc2[wm + (lane >> 2) + 8];
            #pragma unroll
            for (int ni = 0; ni < 2; ni++) {
                O1[ni][0] *= fa1; O1[ni][1] *= fa1; O1[ni][2] *= fb1; O1[ni][3] *= fb1;
                O2[ni][0] *= fa2; O2[ni][1] *= fa2; O2[ni][2] *= fb2; O2[ni][3] *= fb2;
            }
            #pragma unroll
            for (int ks = 0; ks < 4; ks++) {
                uint32_t aoff = SW128((uint32_t)((wm + (lane & 15)) * 128 + ks * 32 + (lane >> 4) * 16));
                uint32_t p1h[4], p1l[4], p2h[4], p2l[4];
                ldsm_x4(p1h, sb + AP1H + aoff); ldsm_x4(p1l, sb + AP1L + aoff);
                ldsm_x4(p2h, sb + AP2H + aoff); ldsm_x4(p2l, sb + AP2L + aoff);
                #pragma unroll
                for (int ni = 0; ni < 2; ni++) {
                    uint32_t boff = SW128((uint32_t)((ks * 16 + (lane & 15)) * 128 + (wn + ni * 8) * 2));
                    uint32_t bvh[2], bvl[2];
                    ldsm_x2t(bvh, sb + bufb + 32768 + boff);
                    ldsm_x2t(bvl, sb + bufb + 40960 + boff);
                    mma16816(O1[ni], p1h, bvh); mma16816(O1[ni], p1h, bvl); mma16816(O1[ni], p1l, bvh);
                    mma16816(O2[ni], p2h, bvh); mma16816(O2[ni], p2h, bvl); mma16816(O2[ni], p2l, bvh);
                }
            }
        }
    }
    __syncthreads();

    // ---- combine & store: O = O1/l1 - lam*O2/l2, (B,S,H,D) ----
    const float lam = lam_p[0];
    {
        int r0 = wm + (lane >> 2), r1 = r0 + 8;
        float i1a = 1.0f / stl1[r0], i1b = 1.0f / stl1[r1];
        float i2a = lam  / stl2[r0], i2b = lam  / stl2[r1];
        #pragma unroll
        for (int ni = 0; ni < 2; ni++) {
            int cc = wn + ni * 8 + (lane & 3) * 2;
            int s0 = q0 + r0, s1r = q0 + r1;
            float2 v0 = { O1[ni][0] * i1a - O2[ni][0] * i2a,
                          O1[ni][1] * i1a - O2[ni][1] * i2a };
            float2 v1 = { O1[ni][2] * i1b - O2[ni][2] * i2b,
                          O1[ni][3] * i1b - O2[ni][3] * i2b };
            *(float2*)(g_attn + (size_t)((b * Sc + s0)  * Hc + h) * Dc + cc) = v0;
            *(float2*)(g_attn + (size_t)((b * Sc + s1r) * Hc + h) * Dc + cc) = v1;
        }
    }
}

// ============================================================
// Group statistics (unchanged)
// ============================================================
__global__ __launch_bounds__(256)
void stats_kernel()
{
    const int b = blockIdx.x >> 3;
    const int j = blockIdx.x & 7;
    const int tid = threadIdx.x;
    double s = 0.0, sq = 0.0;
    const float* base = g_attn + (size_t)b*Sc*Hc*Dc + j*8;
    for (int t = tid; t < Sc*Hc; t += 256) {
        const float* p = base + (size_t)t * 64;
        #pragma unroll
        for (int i = 0; i < 8; i++) {
            float x = p[i];
            s  += (double)x;
            sq += (double)x * (double)x;
        }
    }
    __shared__ double ss[256], sqq[256];
    ss[tid] = s; sqq[tid] = sq;
    __syncthreads();
    for (int o = 128; o > 0; o >>= 1) {
        if (tid < o) { ss[tid] += ss[tid+o]; sqq[tid] += sqq[tid+o]; }
        __syncthreads();
    }
    if (tid == 0) {
        double mean = ss[0] / 65536.0;
        double var  = sqq[0] / 65536.0 - mean * mean;
        g_mean[blockIdx.x] = (float)mean;
        g_rstd[blockIdx.x] = (float)(1.0 / sqrt(var + 1e-3));
    }
}

// ============================================================
// Final elementwise (unchanged)
// ============================================================
__global__ __launch_bounds__(256)
void final_kernel(const float* __restrict__ gamma, const float* __restrict__ beta,
                  const float* __restrict__ li_p, float* __restrict__ out)
{
    const int idx = (blockIdx.x * 256 + threadIdx.x) * 4;
    const int d = idx & 63;
    const int h = (idx >> 6) & 7;
    const int s = (idx >> 9) & 1023;
    const int b = idx >> 19;
    const int j = d >> 3;
    const float mean = g_mean[b*8+j];
    const float rstd = g_rstd[b*8+j];
    const float li = 1.0f - li_p[0];
    float4 a  = *(const float4*)(g_attn + idx);
    float4 g  = *(const float4*)(g_gate + (size_t)((b*Hc+h)*Sc + s)*Dc + d);
    float4 gm = *(const float4*)(gamma + d);
    float4 bt = *(const float4*)(beta + d);
    float4 o;
    o.x = ((a.x-mean)*rstd*gm.x + bt.x) * li * (1.0f/(1.0f+__expf(-g.x)));
    o.y = ((a.y-mean)*rstd*gm.y + bt.y) * li * (1.0f/(1.0f+__expf(-g.y)));
    o.z = ((a.z-mean)*rstd*gm.z + bt.z) * li * (1.0f/(1.0f+__expf(-g.z)));
    o.w = ((a.w-mean)*rstd*gm.w + bt.w) * li * (1.0f/(1.0f+__expf(-g.w)));
    *(float4*)(out + idx) = o;
}

// ============================================================
extern "C" void kernel_launch(void* const* d_in, const int* in_sizes, int n_in,
                              void* d_out, int out_size)
{
    const float* query  = (const float*)d_in[0];
    const float* key    = (const float*)d_in[1];
    const float* values = (const float*)d_in[2];
    const float* Wq = (const float*)d_in[3];
    const float* bq = (const float*)d_in[4];
    const float* Wk = (const float*)d_in[5];
    const float* bk = (const float*)d_in[6];
    const float* Wv = (const float*)d_in[7];
    const float* bv = (const float*)d_in[8];
    const float* gamma = (const float*)d_in[9];
    const float* beta  = (const float*)d_in[10];
    const float* lam   = (const float*)d_in[11];
    const float* lambda_init = (const float*)d_in[12];
    float* out = (float*)d_out;

    cudaFuncSetAttribute(gemm_hmma, cudaFuncAttributeMaxDynamicSharedMemorySize, GEMM_SMEM);
    cudaFuncSetAttribute(attn_hmma, cudaFuncAttributeMaxDynamicSharedMemorySize, ATTN_SMEM);

    // bf16 hi/lo conversions
    convA_kernel<<<4096, 256>>>(query,  0);
    convA_kernel<<<4096, 256>>>(key,    1);
    convA_kernel<<<4096, 256>>>(values, 2);
    convW_kernel<<<dim3(16, 48), 256>>>(Wq, 1536, 0);
    convW_kernel<<<dim3(16, 32), 256>>>(Wk, 1024, 1536*512);
    convW_kernel<<<dim3(16, 16), 256>>>(Wv,  512, 2560*512);

    // HMMA projection GEMMs
    gemm_hmma<<<dim3(64, 12), 256, GEMM_SMEM>>>(0, 0,        bq, 192, 0);
    gemm_hmma<<<dim3(64,  8), 256, GEMM_SMEM>>>(1, 1536*512, bk, 128, 1);
    gemm_hmma<<<dim3(64,  4), 256, GEMM_SMEM>>>(2, 2560*512, bv,  64, 2);

    // HMMA flash attention (512 threads / 16 warps)
    attn_hmma<<<dim3(16, 8, 8), 512, ATTN_SMEM>>>(lam);

    stats_kernel<<<64, 256>>>();
    final_kernel<<<NTOT/1024, 256>>>(gamma, beta, lambda_init, out);
}

// round 7
// speedup vs baseline: 1.2374x; 1.0512x over previous
#include <cuda_runtime.h>
#include <cuda_bf16.h>
#include <math.h>
#include <stdint.h>

#define Bc 8
#define Sc 1024
#define Hc 8
#define Dc 64
#define DMc 512
#define NTOT (Bc*Hc*Sc*Dc)   // 4,194,304

// ---- scratch (device globals; no allocations allowed) ----
__device__ float g_gate[NTOT];   // (B,H,S,D) fp32
__device__ float g_attn[NTOT];   // (B,S,H,D) fp32
__device__ float g_mean[Bc*8];
__device__ float g_rstd[Bc*8];

// bf16 hi/lo attention operands, (B,H,S,D)
__device__ __align__(16) __nv_bfloat16 g_q1h[NTOT], g_q1l[NTOT];
__device__ __align__(16) __nv_bfloat16 g_q2h[NTOT], g_q2l[NTOT];
__device__ __align__(16) __nv_bfloat16 g_k1h[NTOT], g_k1l[NTOT];
__device__ __align__(16) __nv_bfloat16 g_k2h[NTOT], g_k2l[NTOT];
__device__ __align__(16) __nv_bfloat16 g_vh[NTOT],  g_vl[NTOT];

// bf16 hi/lo split operands for tensor-core projection GEMMs
__device__ __align__(16) __nv_bfloat16 g_Ahi[3][8192*512];
__device__ __align__(16) __nv_bfloat16 g_Alo[3][8192*512];
__device__ __align__(16) __nv_bfloat16 g_Whi[3072*512];   // W^T, [N][K] layout
__device__ __align__(16) __nv_bfloat16 g_Wlo[3072*512];

// ============================================================
// helpers
// ============================================================
__device__ __forceinline__ uint32_t smem_u32(const void* p) {
    uint32_t a;
    asm("{ .reg .u64 t; cvta.to.shared.u64 t, %1; cvt.u32.u64 %0, t; }" : "=r"(a) : "l"(p));
    return a;
}
__device__ __forceinline__ void ldsm_x4(uint32_t* r, uint32_t addr) {
    asm volatile("ldmatrix.sync.aligned.m8n8.x4.shared.b16 {%0,%1,%2,%3}, [%4];"
                 : "=r"(r[0]), "=r"(r[1]), "=r"(r[2]), "=r"(r[3]) : "r"(addr));
}
__device__ __forceinline__ void ldsm_x2(uint32_t* r, uint32_t addr) {
    asm volatile("ldmatrix.sync.aligned.m8n8.x2.shared.b16 {%0,%1}, [%2];"
                 : "=r"(r[0]), "=r"(r[1]) : "r"(addr));
}
__device__ __forceinline__ void ldsm_x2t(uint32_t* r, uint32_t addr) {
    asm volatile("ldmatrix.sync.aligned.m8n8.x2.trans.shared.b16 {%0,%1}, [%2];"
                 : "=r"(r[0]), "=r"(r[1]) : "r"(addr));
}
__device__ __forceinline__ void mma16816(float* c, const uint32_t* a, const uint32_t* b) {
    asm volatile("mma.sync.aligned.m16n8k16.row.col.f32.bf16.bf16.f32 "
                 "{%0,%1,%2,%3}, {%4,%5,%6,%7}, {%8,%9}, {%0,%1,%2,%3};"
                 : "+f"(c[0]), "+f"(c[1]), "+f"(c[2]), "+f"(c[3])
                 : "r"(a[0]), "r"(a[1]), "r"(a[2]), "r"(a[3]), "r"(b[0]), "r"(b[1]));
}
__device__ __forceinline__ void cp_async16(uint32_t sa, const void* g) {
    asm volatile("cp.async.cg.shared.global [%0], [%1], 16;" :: "r"(sa), "l"(g) : "memory");
}
#define SW128(off) ((off) ^ (((off) >> 3) & 0x70))

// ============================================================
// Fused conversion kernels (fewer launches; also puts attn at
// launch index 6 so ncu -s 5 -c 1 captures it)
// ============================================================
__global__ __launch_bounds__(256)
void convA_all(const float* __restrict__ Xq, const float* __restrict__ Xk,
               const float* __restrict__ Xv)
{
    const int which = blockIdx.x >> 12;
    const float* X = (which == 0) ? Xq : (which == 1) ? Xk : Xv;
    int i = ((blockIdx.x & 4095) * 256 + threadIdx.x) * 4;
    float4 x = *(const float4*)(X + i);
    __nv_bfloat16 h0 = __float2bfloat16(x.x);
    __nv_bfloat16 h1 = __float2bfloat16(x.y);
    __nv_bfloat16 h2 = __float2bfloat16(x.z);
    __nv_bfloat16 h3 = __float2bfloat16(x.w);
    __nv_bfloat16 l0 = __float2bfloat16(x.x - __bfloat162float(h0));
    __nv_bfloat16 l1 = __float2bfloat16(x.y - __bfloat162float(h1));
    __nv_bfloat16 l2 = __float2bfloat16(x.z - __bfloat162float(h2));
    __nv_bfloat16 l3 = __float2bfloat16(x.w - __bfloat162float(h3));
    __nv_bfloat162* ph = (__nv_bfloat162*)(&g_Ahi[which][i]);
    __nv_bfloat162* pl = (__nv_bfloat162*)(&g_Alo[which][i]);
    ph[0] = __nv_bfloat162(h0, h1); ph[1] = __nv_bfloat162(h2, h3);
    pl[0] = __nv_bfloat162(l0, l1); pl[1] = __nv_bfloat162(l2, l3);
}

// Transpose all three W [K=512][N] -> W^T [N][512] bf16 hi/lo
__global__ __launch_bounds__(256)
void convW_all(const float* __restrict__ Wq, const float* __restrict__ Wk,
               const float* __restrict__ Wv)
{
    __shared__ float t[32][33];
    int by = blockIdx.y;
    const float* W; int N; int off;
    if (by < 48)      { W = Wq; N = 1536; off = 0;           }
    else if (by < 80) { W = Wk; N = 1024; off = 1536*512; by -= 48; }
    else              { W = Wv; N = 512;  off = 2560*512; by -= 80; }
    const int k0 = blockIdx.x * 32;
    const int n0 = by * 32;
    const int tx = threadIdx.x & 31;
    const int ty = threadIdx.x >> 5;
    #pragma unroll
    for (int i = ty; i < 32; i += 8)
        t[i][tx] = W[(size_t)(k0 + i) * N + n0 + tx];
    __syncthreads();
    #pragma unroll
    for (int i = ty; i < 32; i += 8) {
        float x = t[tx][i];
        __nv_bfloat16 h = __float2bfloat16(x);
        size_t idx = (size_t)off + (size_t)(n0 + i) * 512 + k0 + tx;
        g_Whi[idx] = h;
        g_Wlo[idx] = __float2bfloat16(x - __bfloat162float(h));
    }
}

// ============================================================
// HMMA projection GEMM (bf16x3): unchanged (at HMMA roofline)
// ============================================================
#define AH_OFF 0
#define AL_OFF 16384
#define BH_OFF 32768
#define BL_OFF 49152
#define GEMM_SMEM 65536

__global__ __launch_bounds__(256)
void gemm_hmma(int which, int woff, const float* __restrict__ bias, int perHead, int mode)
{
    extern __shared__ __align__(1024) char smem[];
    const uint32_t sbase = smem_u32(smem);
    const int tid = threadIdx.x;
    const int lane = tid & 31;
    const int wid = tid >> 5;
    const int wm = (wid & 1) * 64;
    const int wn = (wid >> 1) * 32;

    const int m0 = blockIdx.x * 128;
    const int n0 = blockIdx.y * 128;

    const __nv_bfloat16* Ahi = g_Ahi[which];
    const __nv_bfloat16* Alo = g_Alo[which];
    const __nv_bfloat16* Whi = g_Whi + (size_t)woff;
    const __nv_bfloat16* Wlo = g_Wlo + (size_t)woff;

    float C[4][4][4];
    #pragma unroll
    for (int i = 0; i < 4; i++)
        #pragma unroll
        for (int j = 0; j < 4; j++)
            #pragma unroll
            for (int c = 0; c < 4; c++) C[i][j][c] = 0.0f;

    for (int kc = 0; kc < 512; kc += 64) {
        #pragma unroll
        for (int i = 0; i < 4; i++) {
            int idx = tid + 256 * i;
            int row = idx >> 3, u = idx & 7;
            uint32_t soff = SW128((uint32_t)(row * 128 + u * 16));
            *(uint4*)(smem + AH_OFF + soff) = *(const uint4*)(Ahi + (size_t)(m0 + row) * 512 + kc + u * 8);
            *(uint4*)(smem + AL_OFF + soff) = *(const uint4*)(Alo + (size_t)(m0 + row) * 512 + kc + u * 8);
            *(uint4*)(smem + BH_OFF + soff) = *(const uint4*)(Whi + (size_t)(n0 + row) * 512 + kc + u * 8);
            *(uint4*)(smem + BL_OFF + soff) = *(const uint4*)(Wlo + (size_t)(n0 + row) * 512 + kc + u * 8);
        }
        __syncthreads();

        #pragma unroll
        for (int ks = 0; ks < 4; ks++) {
            uint32_t ah[4][4], al[4][4];
            #pragma unroll
            for (int mi = 0; mi < 4; mi++) {
                uint32_t off = (uint32_t)((wm + mi * 16 + (lane & 15)) * 128 + ks * 32 + (lane >> 4) * 16);
                off = SW128(off);
                ldsm_x4(ah[mi], sbase + AH_OFF + off);
                ldsm_x4(al[mi], sbase + AL_OFF + off);
            }
            uint32_t bh[4][2], bl[4][2];
            #pragma unroll
            for (int ni = 0; ni < 4; ni++) {
                uint32_t off = (uint32_t)((wn + ni * 8 + (lane & 7)) * 128 + ks * 32 + ((lane >> 3) & 1) * 16);
                off = SW128(off);
                ldsm_x2(bh[ni], sbase + BH_OFF + off);
                ldsm_x2(bl[ni], sbase + BL_OFF + off);
            }
            #pragma unroll
            for (int mi = 0; mi < 4; mi++)
                #pragma unroll
                for (int ni = 0; ni < 4; ni++) {
                    mma16816(C[mi][ni], ah[mi], bh[ni]);
                    mma16816(C[mi][ni], ah[mi], bl[ni]);
                    mma16816(C[mi][ni], al[mi], bh[ni]);
                }
        }
        __syncthreads();
    }

    #pragma unroll
    for (int ni = 0; ni < 4; ni++) {
        const int ng = n0 + wn + ni * 8 + (lane & 3) * 2;
        const int hh  = ng / perHead;
        const int r   = ng % perHead;
        const int seg = r >> 6;
        const int d   = r & 63;
        const float bx = bias[ng], by = bias[ng + 1];
        __nv_bfloat16 *ph = 0, *pl = 0; float* pf = 0;
        if (mode == 0) {
            if (seg == 0)      { ph = g_q1h; pl = g_q1l; }
            else if (seg == 1) { ph = g_q2h; pl = g_q2l; }
            else               { pf = g_gate; }
        } else if (mode == 1) {
            if (seg == 0) { ph = g_k1h; pl = g_k1l; }
            else          { ph = g_k2h; pl = g_k2l; }
        } else { ph = g_vh; pl = g_vl; }
        #pragma unroll
        for (int mi = 0; mi < 4; mi++) {
            #pragma unroll
            for (int half = 0; half < 2; half++) {
                int m = m0 + wm + mi * 16 + (lane >> 2) + half * 8;
                int bb = m >> 10, s = m & 1023;
                size_t idx = (size_t)((bb * Hc + hh) * Sc + s) * Dc + d;
                float v0 = C[mi][ni][half * 2 + 0] + bx;
                float v1 = C[mi][ni][half * 2 + 1] + by;
                if (pf) {
                    *(float2*)(pf + idx) = make_float2(v0, v1);
                } else {
                    __nv_bfloat16 h0 = __float2bfloat16(v0), h1 = __float2bfloat16(v1);
                    __nv_bfloat16 l0 = __float2bfloat16(v0 - __bfloat162float(h0));
                    __nv_bfloat16 l1 = __float2bfloat16(v1 - __bfloat162float(h1));
                    *(__nv_bfloat162*)(ph + idx) = __nv_bfloat162(h0, h1);
                    *(__nv_bfloat162*)(pl + idx) = __nv_bfloat162(l0, l1);
                }
            }
        }
    }
}

// ============================================================
// HMMA flash attention — exact R4 (868us) structure, 256 thr,
// warp grid 4m x 2n, with exp2f + folded scale (only change).
// ============================================================
#define AQ1H 0
#define AQ1L 8192
#define AQ2H 16384
#define AQ2L 24576
#define AKV0 32768
#define KVSZ 49152     // per buf: k1h@0 k1l@8192 k2h@16384 k2l@24576 vh@32768 vl@40960
#define AP1H 131072
#define AP1L 139264
#define AP2H 147456
#define AP2L 155648
#define AS1  163840
#define AS2  180480
#define ASTAT 197120
#define ATTN_SMEM 198656

__global__ __launch_bounds__(256)
void attn_hmma(const float* __restrict__ lam_p)
{
    extern __shared__ __align__(1024) char smem[];
    const uint32_t sb = smem_u32(smem);
    const int tid = threadIdx.x;
    const int lane = tid & 31;
    const int w = tid >> 5;
    const int wm = (w & 3) * 16;
    const int wn = (w >> 2) * 32;

    const int q0 = blockIdx.x * 64;
    const int h = blockIdx.y;
    const int b = blockIdx.z;
    const size_t ho = (size_t)(b * Hc + h) * Sc * Dc;

    const __nv_bfloat16* src[6] = { g_k1h + ho, g_k1l + ho, g_k2h + ho,
                                    g_k2l + ho, g_vh + ho, g_vl + ho };

    float* stm1 = (float*)(smem + ASTAT);
    float* stl1 = stm1 + 64;
    float* stm2 = stl1 + 64;
    float* stl2 = stm2 + 64;
    float* stsc1 = stl2 + 64;
    float* stsc2 = stsc1 + 64;

    // load Q tiles (4 x 64x64 bf16, swizzled)
    {
        const __nv_bfloat16* qs[4] = { g_q1h + ho + (size_t)q0 * Dc, g_q1l + ho + (size_t)q0 * Dc,
                                       g_q2h + ho + (size_t)q0 * Dc, g_q2l + ho + (size_t)q0 * Dc };
        #pragma unroll
        for (int t = 0; t < 4; t++)
            #pragma unroll
            for (int i = 0; i < 2; i++) {
                int idx = tid + 256 * i;
                int row = idx >> 3, u = idx & 7;
                *(uint4*)(smem + t * 8192 + SW128((uint32_t)(row * 128 + u * 16))) =
                    *(const uint4*)(qs[t] + row * 64 + u * 8);
            }
    }
    if (tid < 64) {
        stm1[tid] = -1e30f; stl1[tid] = 0.0f;
        stm2[tid] = -1e30f; stl2[tid] = 0.0f;
    }

    // prologue: KV tile 0 into buffer 0
    {
        #pragma unroll
        for (int t = 0; t < 6; t++)
            #pragma unroll
            for (int i = 0; i < 2; i++) {
                int idx = tid + 256 * i;
                int row = idx >> 3, u = idx & 7;
                cp_async16(sb + AKV0 + t * 8192 + SW128((uint32_t)(row * 128 + u * 16)),
                           src[t] + (size_t)row * 64 + u * 8);
            }
        asm volatile("cp.async.commit_group;" ::: "memory");
    }

    float O1[4][4], O2[4][4];
    #pragma unroll
    for (int ni = 0; ni < 4; ni++)
        #pragma unroll
        for (int c = 0; c < 4; c++) { O1[ni][c] = 0.0f; O2[ni][c] = 0.0f; }

    float* S1F = (float*)(smem + AS1);
    float* S2F = (float*)(smem + AS2);
    const float SC2 = 0.125f * 1.4426950408889634f;   // fold /8 and log2e

    for (int kt = 0; kt < 16; kt++) {
        const uint32_t bufb = AKV0 + (uint32_t)(kt & 1) * KVSZ;
        asm volatile("cp.async.wait_group 0;" ::: "memory");
        __syncthreads();

        // ---- QK^T (both branches, 3-term EC) ----
        float s1[4][4], s2[4][4];
        #pragma unroll
        for (int ni = 0; ni < 4; ni++)
            #pragma unroll
            for (int c = 0; c < 4; c++) { s1[ni][c] = 0.0f; s2[ni][c] = 0.0f; }

        #pragma unroll
        for (int ks = 0; ks < 4; ks++) {
            uint32_t aoff = SW128((uint32_t)((wm + (lane & 15)) * 128 + ks * 32 + (lane >> 4) * 16));
            uint32_t a1h[4], a1l[4], a2h[4], a2l[4];
            ldsm_x4(a1h, sb + AQ1H + aoff); ldsm_x4(a1l, sb + AQ1L + aoff);
            ldsm_x4(a2h, sb + AQ2H + aoff); ldsm_x4(a2l, sb + AQ2L + aoff);
            #pragma unroll
            for (int ni = 0; ni < 4; ni++) {
                uint32_t boff = SW128((uint32_t)((wn + ni * 8 + (lane & 7)) * 128 + ks * 32 + ((lane >> 3) & 1) * 16));
                uint32_t b1h[2], b1l[2], b2h[2], b2l[2];
                ldsm_x2(b1h, sb + bufb + 0     + boff);
                ldsm_x2(b1l, sb + bufb + 8192  + boff);
                ldsm_x2(b2h, sb + bufb + 16384 + boff);
                ldsm_x2(b2l, sb + bufb + 24576 + boff);
                mma16816(s1[ni], a1h, b1h); mma16816(s1[ni], a1h, b1l); mma16816(s1[ni], a1l, b1h);
                mma16816(s2[ni], a2h, b2h); mma16816(s2[ni], a2h, b2l); mma16816(s2[ni], a2l, b2h);
            }
        }
        {
            int r0 = wm + (lane >> 2), r1 = r0 + 8;
            #pragma unroll
            for (int ni = 0; ni < 4; ni++) {
                int cc = wn + ni * 8 + (lane & 3) * 2;
                S1F[r0 * 65 + cc]     = s1[ni][0] * SC2;
                S1F[r0 * 65 + cc + 1] = s1[ni][1] * SC2;
                S1F[r1 * 65 + cc]     = s1[ni][2] * SC2;
                S1F[r1 * 65 + cc + 1] = s1[ni][3] * SC2;
                S2F[r0 * 65 + cc]     = s2[ni][0] * SC2;
                S2F[r0 * 65 + cc + 1] = s2[ni][1] * SC2;
                S2F[r1 * 65 + cc]     = s2[ni][2] * SC2;
                S2F[r1 * 65 + cc + 1] = s2[ni][3] * SC2;
            }
        }

        // prefetch next KV tile (overlaps softmax + PV)
        if (kt < 15) {
            const uint32_t nb = AKV0 + (uint32_t)((kt + 1) & 1) * KVSZ;
            #pragma unroll
            for (int t = 0; t < 6; t++)
                #pragma unroll
                for (int i = 0; i < 2; i++) {
                    int idx = tid + 256 * i;
                    int row = idx >> 3, u = idx & 7;
                    cp_async16(sb + nb + t * 8192 + SW128((uint32_t)(row * 128 + u * 16)),
                               src[t] + (size_t)((kt + 1) * 64 + row) * 64 + u * 8);
                }
            asm volatile("cp.async.commit_group;" ::: "memory");
        }
        __syncthreads();

        // ---- online softmax (log2 domain), write P bf16 hi/lo ----
        {
            const int row = tid >> 2;
            const int base = (tid & 3) * 16;

            // branch 1
            float mx = -1e30f;
            #pragma unroll
            for (int c = 0; c < 16; c++) mx = fmaxf(mx, S1F[row * 65 + base + c]);
            mx = fmaxf(mx, __shfl_xor_sync(0xffffffffu, mx, 1));
            mx = fmaxf(mx, __shfl_xor_sync(0xffffffffu, mx, 2));
            float mold = stm1[row];
            float mnew = fmaxf(mold, mx);
            float sum = 0.0f;
            #pragma unroll
            for (int c = 0; c < 16; c += 2) {
                float p0 = exp2f(S1F[row * 65 + base + c]     - mnew);
                float p1 = exp2f(S1F[row * 65 + base + c + 1] - mnew);
                sum += p0 + p1;
                __nv_bfloat16 h0 = __float2bfloat16(p0), h1 = __float2bfloat16(p1);
                __nv_bfloat16 l0 = __float2bfloat16(p0 - __bfloat162float(h0));
                __nv_bfloat16 l1 = __float2bfloat16(p1 - __bfloat162float(h1));
                uint32_t off = SW128((uint32_t)(row * 128 + (base + c) * 2));
                *(__nv_bfloat162*)(smem + AP1H + off) = __nv_bfloat162(h0, h1);
                *(__nv_bfloat162*)(smem + AP1L + off) = __nv_bfloat162(l0, l1);
            }
            sum += __shfl_xor_sync(0xffffffffu, sum, 1);
            sum += __shfl_xor_sync(0xffffffffu, sum, 2);
            if ((tid & 3) == 0) {
                float scl = exp2f(mold - mnew);
                stsc1[row] = scl;
                stl1[row] = stl1[row] * scl + sum;
                stm1[row] = mnew;
            }

            // branch 2
            mx = -1e30f;
            #pragma unroll
            for (int c = 0; c < 16; c++) mx = fmaxf(mx, S2F[row * 65 + base + c]);
            mx = fmaxf(mx, __shfl_xor_sync(0xffffffffu, mx, 1));
            mx = fmaxf(mx, __shfl_xor_sync(0xffffffffu, mx, 2));
            mold = stm2[row];
            mnew = fmaxf(mold, mx);
            sum = 0.0f;
            #pragma unroll
            for (int c = 0; c < 16; c += 2) {
                float p0 = exp2f(S2F[row * 65 + base + c]     - mnew);
                float p1 = exp2f(S2F[row * 65 + base + c + 1] - mnew);
                sum += p0 + p1;
                __nv_bfloat16 h0 = __float2bfloat16(p0), h1 = __float2bfloat16(p1);
                __nv_bfloat16 l0 = __float2bfloat16(p0 - __bfloat162float(h0));
                __nv_bfloat16 l1 = __float2bfloat16(p1 - __bfloat162float(h1));
                uint32_t off = SW128((uint32_t)(row * 128 + (base + c) * 2));
                *(__nv_bfloat162*)(smem + AP2H + off) = __nv_bfloat162(h0, h1);
                *(__nv_bfloat162*)(smem + AP2L + off) = __nv_bfloat162(l0, l1);
            }
            sum += __shfl_xor_sync(0xffffffffu, sum, 1);
            sum += __shfl_xor_sync(0xffffffffu, sum, 2);
            if ((tid & 3) == 0) {
                float scl = exp2f(mold - mnew);
                stsc2[row] = scl;
                stl2[row] = stl2[row] * scl + sum;
                stm2[row] = mnew;
            }
        }
        __syncthreads();

        // ---- rescale O, then O += P V ----
        {
            float fa1 = stsc1[wm + (lane >> 2)], fb1 = stsc1[wm + (lane >> 2) + 8];
            float fa2 = stsc2[wm + (lane >> 2)], fb2 = stsc2[wm + (lane >> 2) + 8];
            #pragma unroll
            for (int ni = 0; ni < 4; ni++) {
                O1[ni][0] *= fa1; O1[ni][1] *= fa1; O1[ni][2] *= fb1; O1[ni][3] *= fb1;
                O2[ni][0] *= fa2; O2[ni][1] *= fa2; O2[ni][2] *= fb2; O2[ni][3] *= fb2;
            }
            #pragma unroll
            for (int ks = 0; ks < 4; ks++) {
                uint32_t aoff = SW128((uint32_t)((wm + (lane & 15)) * 128 + ks * 32 + (lane >> 4) * 16));
                uint32_t p1h[4], p1l[4], p2h[4], p2l[4];
                ldsm_x4(p1h, sb + AP1H + aoff); ldsm_x4(p1l, sb + AP1L + aoff);
                ldsm_x4(p2h, sb + AP2H + aoff); ldsm_x4(p2l, sb + AP2L + aoff);
                #pragma unroll
                for (int ni = 0; ni < 4; ni++) {
                    uint32_t boff = SW128((uint32_t)((ks * 16 + (lane & 15)) * 128 + (wn + ni * 8) * 2));
                    uint32_t bvh[2], bvl[2];
                    ldsm_x2t(bvh, sb + bufb + 32768 + boff);
                    ldsm_x2t(bvl, sb + bufb + 40960 + boff);
                    mma16816(O1[ni], p1h, bvh); mma16816(O1[ni], p1h, bvl); mma16816(O1[ni], p1l, bvh);
                    mma16816(O2[ni], p2h, bvh); mma16816(O2[ni], p2h, bvl); mma16816(O2[ni], p2l, bvh);
                }
            }
        }
    }
    __syncthreads();

    // ---- combine & store: O = O1/l1 - lam*O2/l2, (B,S,H,D) ----
    const float lam = lam_p[0];
    {
        int r0 = wm + (lane >> 2), r1 = r0 + 8;
        float i1a = 1.0f / stl1[r0], i1b = 1.0f / stl1[r1];
        float i2a = lam  / stl2[r0], i2b = lam  / stl2[r1];
        #pragma unroll
        for (int ni = 0; ni < 4; ni++) {
            int cc = wn + ni * 8 + (lane & 3) * 2;
            int s0 = q0 + r0, s1r = q0 + r1;
            float2 v0 = { O1[ni][0] * i1a - O2[ni][0] * i2a,
                          O1[ni][1] * i1a - O2[ni][1] * i2a };
            float2 v1 = { O1[ni][2] * i1b - O2[ni][2] * i2b,
                          O1[ni][3] * i1b - O2[ni][3] * i2b };
            *(float2*)(g_attn + (size_t)((b * Sc + s0)  * Hc + h) * Dc + cc) = v0;
            *(float2*)(g_attn + (size_t)((b * Sc + s1r) * Hc + h) * Dc + cc) = v1;
        }
    }
}

// ============================================================
// Group statistics (unchanged)
// ============================================================
__global__ __launch_bounds__(256)
void stats_kernel()
{
    const int b = blockIdx.x >> 3;
    const int j = blockIdx.x & 7;
    const int tid = threadIdx.x;
    double s = 0.0, sq = 0.0;
    const float* base = g_attn + (size_t)b*Sc*Hc*Dc + j*8;
    for (int t = tid; t < Sc*Hc; t += 256) {
        const float* p = base + (size_t)t * 64;
        #pragma unroll
        for (int i = 0; i < 8; i++) {
            float x = p[i];
            s  += (double)x;
            sq += (double)x * (double)x;
        }
    }
    __shared__ double ss[256], sqq[256];
    ss[tid] = s; sqq[tid] = sq;
    __syncthreads();
    for (int o = 128; o > 0; o >>= 1) {
        if (tid < o) { ss[tid] += ss[tid+o]; sqq[tid] += sqq[tid+o]; }
        __syncthreads();
    }
    if (tid == 0) {
        double mean = ss[0] / 65536.0;
        double var  = sqq[0] / 65536.0 - mean * mean;
        g_mean[blockIdx.x] = (float)mean;
        g_rstd[blockIdx.x] = (float)(1.0 / sqrt(var + 1e-3));
    }
}

// ============================================================
// Final elementwise (unchanged)
// ============================================================
__global__ __launch_bounds__(256)
void final_kernel(const float* __restrict__ gamma, const float* __restrict__ beta,
                  const float* __restrict__ li_p, float* __restrict__ out)
{
    const int idx = (blockIdx.x * 256 + threadIdx.x) * 4;
    const int d = idx & 63;
    const int h = (idx >> 6) & 7;
    const int s = (idx >> 9) & 1023;
    const int b = idx >> 19;
    const int j = d >> 3;
    const float mean = g_mean[b*8+j];
    const float rstd = g_rstd[b*8+j];
    const float li = 1.0f - li_p[0];
    float4 a  = *(const float4*)(g_attn + idx);
    float4 g  = *(const float4*)(g_gate + (size_t)((b*Hc+h)*Sc + s)*Dc + d);
    float4 gm = *(const float4*)(gamma + d);
    float4 bt = *(const float4*)(beta + d);
    float4 o;
    o.x = ((a.x-mean)*rstd*gm.x + bt.x) * li * (1.0f/(1.0f+__expf(-g.x)));
    o.y = ((a.y-mean)*rstd*gm.y + bt.y) * li * (1.0f/(1.0f+__expf(-g.y)));
    o.z = ((a.z-mean)*rstd*gm.z + bt.z) * li * (1.0f/(1.0f+__expf(-g.z)));
    o.w = ((a.w-mean)*rstd*gm.w + bt.w) * li * (1.0f/(1.0f+__expf(-g.w)));
    *(float4*)(out + idx) = o;
}

// ============================================================
extern "C" void kernel_launch(void* const* d_in, const int* in_sizes, int n_in,
                              void* d_out, int out_size)
{
    const float* query  = (const float*)d_in[0];
    const float* key    = (const float*)d_in[1];
    const float* values = (const float*)d_in[2];
    const float* Wq = (const float*)d_in[3];
    const float* bq = (const float*)d_in[4];
    const float* Wk = (const float*)d_in[5];
    const float* bk = (const float*)d_in[6];
    const float* Wv = (const float*)d_in[7];
    const float* bv = (const float*)d_in[8];
    const float* gamma = (const float*)d_in[9];
    const float* beta  = (const float*)d_in[10];
    const float* lam   = (const float*)d_in[11];
    const float* lambda_init = (const float*)d_in[12];
    float* out = (float*)d_out;

    cudaFuncSetAttribute(gemm_hmma, cudaFuncAttributeMaxDynamicSharedMemorySize, GEMM_SMEM);
    cudaFuncSetAttribute(attn_hmma, cudaFuncAttributeMaxDynamicSharedMemorySize, ATTN_SMEM);

    // launch 1-2: fused conversions
    convA_all<<<12288, 256>>>(query, key, values);
    convW_all<<<dim3(16, 96), 256>>>(Wq, Wk, Wv);

    // launch 3-5: HMMA projection GEMMs
    gemm_hmma<<<dim3(64, 12), 256, GEMM_SMEM>>>(0, 0,        bq, 192, 0);
    gemm_hmma<<<dim3(64,  8), 256, GEMM_SMEM>>>(1, 1536*512, bk, 128, 1);
    gemm_hmma<<<dim3(64,  4), 256, GEMM_SMEM>>>(2, 2560*512, bv,  64, 2);

    // launch 6 (ncu -s 5 -c 1 captures this): HMMA flash attention
    attn_hmma<<<dim3(16, 8, 8), 256, ATTN_SMEM>>>(lam);

    stats_kernel<<<64, 256>>>();
    final_kernel<<<NTOT/1024, 256>>>(gamma, beta, lambda_init, out);
}

// round 8
// speedup vs baseline: 1.5240x; 1.2316x over previous
#include <cuda_runtime.h>
#include <cuda_bf16.h>
#include <math.h>
#include <stdint.h>

#define Bc 8
#define Sc 1024
#define Hc 8
#define Dc 64
#define DMc 512
#define NTOT (Bc*Hc*Sc*Dc)   // 4,194,304

// ---- scratch (device globals; no allocations allowed) ----
__device__ float g_gate[NTOT];   // (B,H,S,D) fp32
__device__ float g_attn[NTOT];   // (B,S,H,D) fp32
__device__ float g_mean[Bc*8];
__device__ float g_rstd[Bc*8];

// bf16 hi/lo attention operands, (B,H,S,D)
__device__ __align__(16) __nv_bfloat16 g_q1h[NTOT], g_q1l[NTOT];
__device__ __align__(16) __nv_bfloat16 g_q2h[NTOT], g_q2l[NTOT];
__device__ __align__(16) __nv_bfloat16 g_k1h[NTOT], g_k1l[NTOT];
__device__ __align__(16) __nv_bfloat16 g_k2h[NTOT], g_k2l[NTOT];
__device__ __align__(16) __nv_bfloat16 g_vh[NTOT],  g_vl[NTOT];

// bf16 hi/lo split operands for tensor-core projection GEMMs
__device__ __align__(16) __nv_bfloat16 g_Ahi[3][8192*512];
__device__ __align__(16) __nv_bfloat16 g_Alo[3][8192*512];
__device__ __align__(16) __nv_bfloat16 g_Whi[3072*512];   // W^T, [N][K] layout
__device__ __align__(16) __nv_bfloat16 g_Wlo[3072*512];

// ============================================================
// helpers
// ============================================================
__device__ __forceinline__ uint32_t smem_u32(const void* p) {
    uint32_t a;
    asm("{ .reg .u64 t; cvta.to.shared.u64 t, %1; cvt.u32.u64 %0, t; }" : "=r"(a) : "l"(p));
    return a;
}
__device__ __forceinline__ void ldsm_x4(uint32_t* r, uint32_t addr) {
    asm volatile("ldmatrix.sync.aligned.m8n8.x4.shared.b16 {%0,%1,%2,%3}, [%4];"
                 : "=r"(r[0]), "=r"(r[1]), "=r"(r[2]), "=r"(r[3]) : "r"(addr));
}
__device__ __forceinline__ void ldsm_x2(uint32_t* r, uint32_t addr) {
    asm volatile("ldmatrix.sync.aligned.m8n8.x2.shared.b16 {%0,%1}, [%2];"
                 : "=r"(r[0]), "=r"(r[1]) : "r"(addr));
}
__device__ __forceinline__ void ldsm_x2t(uint32_t* r, uint32_t addr) {
    asm volatile("ldmatrix.sync.aligned.m8n8.x2.trans.shared.b16 {%0,%1}, [%2];"
                 : "=r"(r[0]), "=r"(r[1]) : "r"(addr));
}
__device__ __forceinline__ void mma16816(float* c, const uint32_t* a, const uint32_t* b) {
    asm volatile("mma.sync.aligned.m16n8k16.row.col.f32.bf16.bf16.f32 "
                 "{%0,%1,%2,%3}, {%4,%5,%6,%7}, {%8,%9}, {%0,%1,%2,%3};"
                 : "+f"(c[0]), "+f"(c[1]), "+f"(c[2]), "+f"(c[3])
                 : "r"(a[0]), "r"(a[1]), "r"(a[2]), "r"(a[3]), "r"(b[0]), "r"(b[1]));
}
__device__ __forceinline__ void cp_async16(uint32_t sa, const void* g) {
    asm volatile("cp.async.cg.shared.global [%0], [%1], 16;" :: "r"(sa), "l"(g) : "memory");
}
__device__ __forceinline__ uint32_t packbf(__nv_bfloat16 a, __nv_bfloat16 b) {
    return (uint32_t)__bfloat16_as_ushort(a) | ((uint32_t)__bfloat16_as_ushort(b) << 16);
}
#define SW128(off) ((off) ^ (((off) >> 3) & 0x70))

// ============================================================
// Fused conversion kernels
// ============================================================
__global__ __launch_bounds__(256)
void convA_all(const float* __restrict__ Xq, const float* __restrict__ Xk,
               const float* __restrict__ Xv)
{
    const int which = blockIdx.x >> 12;
    const float* X = (which == 0) ? Xq : (which == 1) ? Xk : Xv;
    int i = ((blockIdx.x & 4095) * 256 + threadIdx.x) * 4;
    float4 x = *(const float4*)(X + i);
    __nv_bfloat16 h0 = __float2bfloat16(x.x);
    __nv_bfloat16 h1 = __float2bfloat16(x.y);
    __nv_bfloat16 h2 = __float2bfloat16(x.z);
    __nv_bfloat16 h3 = __float2bfloat16(x.w);
    __nv_bfloat16 l0 = __float2bfloat16(x.x - __bfloat162float(h0));
    __nv_bfloat16 l1 = __float2bfloat16(x.y - __bfloat162float(h1));
    __nv_bfloat16 l2 = __float2bfloat16(x.z - __bfloat162float(h2));
    __nv_bfloat16 l3 = __float2bfloat16(x.w - __bfloat162float(h3));
    __nv_bfloat162* ph = (__nv_bfloat162*)(&g_Ahi[which][i]);
    __nv_bfloat162* pl = (__nv_bfloat162*)(&g_Alo[which][i]);
    ph[0] = __nv_bfloat162(h0, h1); ph[1] = __nv_bfloat162(h2, h3);
    pl[0] = __nv_bfloat162(l0, l1); pl[1] = __nv_bfloat162(l2, l3);
}

__global__ __launch_bounds__(256)
void convW_all(const float* __restrict__ Wq, const float* __restrict__ Wk,
               const float* __restrict__ Wv)
{
    __shared__ float t[32][33];
    int by = blockIdx.y;
    const float* W; int N; int off;
    if (by < 48)      { W = Wq; N = 1536; off = 0;           }
    else if (by < 80) { W = Wk; N = 1024; off = 1536*512; by -= 48; }
    else              { W = Wv; N = 512;  off = 2560*512; by -= 80; }
    const int k0 = blockIdx.x * 32;
    const int n0 = by * 32;
    const int tx = threadIdx.x & 31;
    const int ty = threadIdx.x >> 5;
    #pragma unroll
    for (int i = ty; i < 32; i += 8)
        t[i][tx] = W[(size_t)(k0 + i) * N + n0 + tx];
    __syncthreads();
    #pragma unroll
    for (int i = ty; i < 32; i += 8) {
        float x = t[tx][i];
        __nv_bfloat16 h = __float2bfloat16(x);
        size_t idx = (size_t)off + (size_t)(n0 + i) * 512 + k0 + tx;
        g_Whi[idx] = h;
        g_Wlo[idx] = __float2bfloat16(x - __bfloat162float(h));
    }
}

// ============================================================
// HMMA projection GEMM (bf16x3) — now 2 CTAs/SM via launch
// bounds (was regs=142 -> occ 12.5%, tensor 36%)
// ============================================================
#define AH_OFF 0
#define AL_OFF 16384
#define BH_OFF 32768
#define BL_OFF 49152
#define GEMM_SMEM 65536

__global__ __launch_bounds__(256, 2)
void gemm_hmma(int which, int woff, const float* __restrict__ bias, int perHead, int mode)
{
    extern __shared__ __align__(1024) char smem[];
    const uint32_t sbase = smem_u32(smem);
    const int tid = threadIdx.x;
    const int lane = tid & 31;
    const int wid = tid >> 5;
    const int wm = (wid & 1) * 64;
    const int wn = (wid >> 1) * 32;

    const int m0 = blockIdx.x * 128;
    const int n0 = blockIdx.y * 128;

    const __nv_bfloat16* Ahi = g_Ahi[which];
    const __nv_bfloat16* Alo = g_Alo[which];
    const __nv_bfloat16* Whi = g_Whi + (size_t)woff;
    const __nv_bfloat16* Wlo = g_Wlo + (size_t)woff;

    float C[4][4][4];
    #pragma unroll
    for (int i = 0; i < 4; i++)
        #pragma unroll
        for (int j = 0; j < 4; j++)
            #pragma unroll
            for (int c = 0; c < 4; c++) C[i][j][c] = 0.0f;

    for (int kc = 0; kc < 512; kc += 64) {
        #pragma unroll
        for (int i = 0; i < 4; i++) {
            int idx = tid + 256 * i;
            int row = idx >> 3, u = idx & 7;
            uint32_t soff = SW128((uint32_t)(row * 128 + u * 16));
            *(uint4*)(smem + AH_OFF + soff) = *(const uint4*)(Ahi + (size_t)(m0 + row) * 512 + kc + u * 8);
            *(uint4*)(smem + AL_OFF + soff) = *(const uint4*)(Alo + (size_t)(m0 + row) * 512 + kc + u * 8);
            *(uint4*)(smem + BH_OFF + soff) = *(const uint4*)(Whi + (size_t)(n0 + row) * 512 + kc + u * 8);
            *(uint4*)(smem + BL_OFF + soff) = *(const uint4*)(Wlo + (size_t)(n0 + row) * 512 + kc + u * 8);
        }
        __syncthreads();

        #pragma unroll
        for (int ks = 0; ks < 4; ks++) {
            uint32_t ah[4][4], al[4][4];
            #pragma unroll
            for (int mi = 0; mi < 4; mi++) {
                uint32_t off = (uint32_t)((wm + mi * 16 + (lane & 15)) * 128 + ks * 32 + (lane >> 4) * 16);
                off = SW128(off);
                ldsm_x4(ah[mi], sbase + AH_OFF + off);
                ldsm_x4(al[mi], sbase + AL_OFF + off);
            }
            uint32_t bh[4][2], bl[4][2];
            #pragma unroll
            for (int ni = 0; ni < 4; ni++) {
                uint32_t off = (uint32_t)((wn + ni * 8 + (lane & 7)) * 128 + ks * 32 + ((lane >> 3) & 1) * 16);
                off = SW128(off);
                ldsm_x2(bh[ni], sbase + BH_OFF + off);
                ldsm_x2(bl[ni], sbase + BL_OFF + off);
            }
            #pragma unroll
            for (int mi = 0; mi < 4; mi++)
                #pragma unroll
                for (int ni = 0; ni < 4; ni++) {
                    mma16816(C[mi][ni], ah[mi], bh[ni]);
                    mma16816(C[mi][ni], ah[mi], bl[ni]);
                    mma16816(C[mi][ni], al[mi], bh[ni]);
                }
        }
        __syncthreads();
    }

    #pragma unroll
    for (int ni = 0; ni < 4; ni++) {
        const int ng = n0 + wn + ni * 8 + (lane & 3) * 2;
        const int hh  = ng / perHead;
        const int r   = ng % perHead;
        const int seg = r >> 6;
        const int d   = r & 63;
        const float bx = bias[ng], by = bias[ng + 1];
        __nv_bfloat16 *ph = 0, *pl = 0; float* pf = 0;
        if (mode == 0) {
            if (seg == 0)      { ph = g_q1h; pl = g_q1l; }
            else if (seg == 1) { ph = g_q2h; pl = g_q2l; }
            else               { pf = g_gate; }
        } else if (mode == 1) {
            if (seg == 0) { ph = g_k1h; pl = g_k1l; }
            else          { ph = g_k2h; pl = g_k2l; }
        } else { ph = g_vh; pl = g_vl; }
        #pragma unroll
        for (int mi = 0; mi < 4; mi++) {
            #pragma unroll
            for (int half = 0; half < 2; half++) {
                int m = m0 + wm + mi * 16 + (lane >> 2) + half * 8;
                int bb = m >> 10, s = m & 1023;
                size_t idx = (size_t)((bb * Hc + hh) * Sc + s) * Dc + d;
                float v0 = C[mi][ni][half * 2 + 0] + bx;
                float v1 = C[mi][ni][half * 2 + 1] + by;
                if (pf) {
                    *(float2*)(pf + idx) = make_float2(v0, v1);
                } else {
                    __nv_bfloat16 h0 = __float2bfloat16(v0), h1 = __float2bfloat16(v1);
                    __nv_bfloat16 l0 = __float2bfloat16(v0 - __bfloat162float(h0));
                    __nv_bfloat16 l1 = __float2bfloat16(v1 - __bfloat162float(h1));
                    *(__nv_bfloat162*)(ph + idx) = __nv_bfloat162(h0, h1);
                    *(__nv_bfloat162*)(pl + idx) = __nv_bfloat162(l0, l1);
                }
            }
        }
    }
}

// ============================================================
// HMMA flash attention v3: fragment-resident softmax.
// Warp w: rows wm..wm+15, key-half (w>>2)*32..+32. QK C-frags
// become PV A-frags directly (no S/P smem round trip).
// O partials (key-split) summed across warp pairs at the end.
// ============================================================
#define AQ1H 0
#define AQ1L 8192
#define AQ2H 16384
#define AQ2L 24576
#define AKV0 32768
#define KVSZ 49152     // per buf: k1h@0 k1l@8192 k2h@16384 k2l@24576 vh@32768 vl@40960
#define APM  131072    // partial max  [half][branch][64] = 1KB
#define APS  132096    // partial sum  [half][branch][64] = 1KB
#define ACMB 133120    // combine 64 x 66 fp32
#define ATTN_SMEM 150016

__global__ __launch_bounds__(256)
void attn_hmma(const float* __restrict__ lam_p)
{
    extern __shared__ __align__(1024) char smem[];
    const uint32_t sb = smem_u32(smem);
    const int tid = threadIdx.x;
    const int lane = tid & 31;
    const int w = tid >> 5;
    const int wm = (w & 3) * 16;       // row block
    const int half = w >> 2;           // key half (0 or 1)
    const int kh = half * 32;          // key offset within 64-key tile

    const int q0 = blockIdx.x * 64;
    const int h = blockIdx.y;
    const int b = blockIdx.z;
    const size_t ho = (size_t)(b * Hc + h) * Sc * Dc;

    const __nv_bfloat16* src[6] = { g_k1h + ho, g_k1l + ho, g_k2h + ho,
                                    g_k2l + ho, g_vh + ho, g_vl + ho };

    // load Q tiles (4 x 64x64 bf16, swizzled)
    {
        const __nv_bfloat16* qs[4] = { g_q1h + ho + (size_t)q0 * Dc, g_q1l + ho + (size_t)q0 * Dc,
                                       g_q2h + ho + (size_t)q0 * Dc, g_q2l + ho + (size_t)q0 * Dc };
        #pragma unroll
        for (int t = 0; t < 4; t++)
            #pragma unroll
            for (int i = 0; i < 2; i++) {
                int idx = tid + 256 * i;
                int row = idx >> 3, u = idx & 7;
                *(uint4*)(smem + t * 8192 + SW128((uint32_t)(row * 128 + u * 16))) =
                    *(const uint4*)(qs[t] + row * 64 + u * 8);
            }
    }
    // prologue: KV tile 0 into buffer 0
    {
        #pragma unroll
        for (int t = 0; t < 6; t++)
            #pragma unroll
            for (int i = 0; i < 2; i++) {
                int idx = tid + 256 * i;
                int row = idx >> 3, u = idx & 7;
                cp_async16(sb + AKV0 + t * 8192 + SW128((uint32_t)(row * 128 + u * 16)),
                           src[t] + (size_t)row * 64 + u * 8);
            }
        asm volatile("cp.async.commit_group;" ::: "memory");
    }

    float O1[8][4], O2[8][4];
    #pragma unroll
    for (int nd = 0; nd < 8; nd++)
        #pragma unroll
        for (int c = 0; c < 4; c++) { O1[nd][c] = 0.0f; O2[nd][c] = 0.0f; }
    // per-thread row stats: rows r0 = wm + lane/4 ('a') and r0+8 ('b')
    float m1a = -1e30f, m1b = -1e30f, m2a = -1e30f, m2b = -1e30f;
    float l1a = 0.0f, l1b = 0.0f, l2a = 0.0f, l2b = 0.0f;

    float* pm = (float*)(smem + APM);   // [half*2 + branch][64]
    float* ps = (float*)(smem + APS);
    const int r0 = wm + (lane >> 2);
    const float SC2 = 0.125f * 1.4426950408889634f;   // /8 and log2e folded

    for (int kt = 0; kt < 16; kt++) {
        const uint32_t bufb = AKV0 + (uint32_t)(kt & 1) * KVSZ;
        asm volatile("cp.async.wait_group 0;" ::: "memory");
        __syncthreads();

        // ---- QK^T for this warp's 16 rows x 32-key half (3-term EC) ----
        float s1[4][4], s2[4][4];
        #pragma unroll
        for (int ni = 0; ni < 4; ni++)
            #pragma unroll
            for (int c = 0; c < 4; c++) { s1[ni][c] = 0.0f; s2[ni][c] = 0.0f; }

        #pragma unroll
        for (int ks = 0; ks < 4; ks++) {
            uint32_t aoff = SW128((uint32_t)((wm + (lane & 15)) * 128 + ks * 32 + (lane >> 4) * 16));
            uint32_t a1h[4], a1l[4], a2h[4], a2l[4];
            ldsm_x4(a1h, sb + AQ1H + aoff); ldsm_x4(a1l, sb + AQ1L + aoff);
            ldsm_x4(a2h, sb + AQ2H + aoff); ldsm_x4(a2l, sb + AQ2L + aoff);
            #pragma unroll
            for (int ni = 0; ni < 4; ni++) {
                uint32_t boff = SW128((uint32_t)((kh + ni * 8 + (lane & 7)) * 128 + ks * 32 + ((lane >> 3) & 1) * 16));
                uint32_t b1h[2], b1l[2], b2h[2], b2l[2];
                ldsm_x2(b1h, sb + bufb + 0     + boff);
                ldsm_x2(b1l, sb + bufb + 8192  + boff);
                ldsm_x2(b2h, sb + bufb + 16384 + boff);
                ldsm_x2(b2l, sb + bufb + 24576 + boff);
                mma16816(s1[ni], a1h, b1h); mma16816(s1[ni], a1h, b1l); mma16816(s1[ni], a1l, b1h);
                mma16816(s2[ni], a2h, b2h); mma16816(s2[ni], a2h, b2l); mma16816(s2[ni], a2l, b2h);
            }
        }

        // prefetch next KV tile (overlaps softmax + PV)
        if (kt < 15) {
            const uint32_t nb = AKV0 + (uint32_t)((kt + 1) & 1) * KVSZ;
            #pragma unroll
            for (int t = 0; t < 6; t++)
                #pragma unroll
                for (int i = 0; i < 2; i++) {
                    int idx = tid + 256 * i;
                    int row = idx >> 3, u = idx & 7;
                    cp_async16(sb + nb + t * 8192 + SW128((uint32_t)(row * 128 + u * 16)),
                               src[t] + (size_t)((kt + 1) * 64 + row) * 64 + u * 8);
                }
            asm volatile("cp.async.commit_group;" ::: "memory");
        }

        // ---- scale + warp-half row max ----
        float x1a = -1e30f, x1b = -1e30f, x2a = -1e30f, x2b = -1e30f;
        #pragma unroll
        for (int ni = 0; ni < 4; ni++) {
            s1[ni][0] *= SC2; s1[ni][1] *= SC2; s1[ni][2] *= SC2; s1[ni][3] *= SC2;
            s2[ni][0] *= SC2; s2[ni][1] *= SC2; s2[ni][2] *= SC2; s2[ni][3] *= SC2;
            x1a = fmaxf(x1a, fmaxf(s1[ni][0], s1[ni][1]));
            x1b = fmaxf(x1b, fmaxf(s1[ni][2], s1[ni][3]));
            x2a = fmaxf(x2a, fmaxf(s2[ni][0], s2[ni][1]));
            x2b = fmaxf(x2b, fmaxf(s2[ni][2], s2[ni][3]));
        }
        x1a = fmaxf(x1a, __shfl_xor_sync(0xffffffffu, x1a, 1));
        x1a = fmaxf(x1a, __shfl_xor_sync(0xffffffffu, x1a, 2));
        x1b = fmaxf(x1b, __shfl_xor_sync(0xffffffffu, x1b, 1));
        x1b = fmaxf(x1b, __shfl_xor_sync(0xffffffffu, x1b, 2));
        x2a = fmaxf(x2a, __shfl_xor_sync(0xffffffffu, x2a, 1));
        x2a = fmaxf(x2a, __shfl_xor_sync(0xffffffffu, x2a, 2));
        x2b = fmaxf(x2b, __shfl_xor_sync(0xffffffffu, x2b, 1));
        x2b = fmaxf(x2b, __shfl_xor_sync(0xffffffffu, x2b, 2));
        if ((lane & 3) == 0) {
            pm[(half * 2 + 0) * 64 + r0]     = x1a;
            pm[(half * 2 + 0) * 64 + r0 + 8] = x1b;
            pm[(half * 2 + 1) * 64 + r0]     = x2a;
            pm[(half * 2 + 1) * 64 + r0 + 8] = x2b;
        }
        __syncthreads();
        {
            const int oh = 1 - half;
            x1a = fmaxf(x1a, pm[(oh * 2 + 0) * 64 + r0]);
            x1b = fmaxf(x1b, pm[(oh * 2 + 0) * 64 + r0 + 8]);
            x2a = fmaxf(x2a, pm[(oh * 2 + 1) * 64 + r0]);
            x2b = fmaxf(x2b, pm[(oh * 2 + 1) * 64 + r0 + 8]);
        }
        const float mn1a = fmaxf(m1a, x1a), mn1b = fmaxf(m1b, x1b);
        const float mn2a = fmaxf(m2a, x2a), mn2b = fmaxf(m2b, x2b);
        const float sc1a = exp2f(m1a - mn1a), sc1b = exp2f(m1b - mn1b);
        const float sc2a = exp2f(m2a - mn2a), sc2b = exp2f(m2b - mn2b);
        m1a = mn1a; m1b = mn1b; m2a = mn2a; m2b = mn2b;

        // ---- exp on fragments, pack directly into PV A-frags ----
        uint32_t p1h[2][4], p1l[2][4], p2h[2][4], p2l[2][4];
        float su1a = 0.0f, su1b = 0.0f, su2a = 0.0f, su2b = 0.0f;
        #pragma unroll
        for (int j = 0; j < 2; j++) {
            #pragma unroll
            for (int e = 0; e < 2; e++) {
                const int ni = 2 * j + e;
                float q0v = exp2f(s1[ni][0] - mn1a);
                float q1v = exp2f(s1[ni][1] - mn1a);
                float q2v = exp2f(s1[ni][2] - mn1b);
                float q3v = exp2f(s1[ni][3] - mn1b);
                su1a += q0v + q1v; su1b += q2v + q3v;
                __nv_bfloat16 h0 = __float2bfloat16(q0v), h1 = __float2bfloat16(q1v);
                __nv_bfloat16 h2 = __float2bfloat16(q2v), h3 = __float2bfloat16(q3v);
                p1h[j][2 * e]     = packbf(h0, h1);
                p1h[j][2 * e + 1] = packbf(h2, h3);
                p1l[j][2 * e]     = packbf(__float2bfloat16(q0v - __bfloat162float(h0)),
                                           __float2bfloat16(q1v - __bfloat162float(h1)));
                p1l[j][2 * e + 1] = packbf(__float2bfloat16(q2v - __bfloat162float(h2)),
                                           __float2bfloat16(q3v - __bfloat162float(h3)));

                q0v = exp2f(s2[ni][0] - mn2a);
                q1v = exp2f(s2[ni][1] - mn2a);
                q2v = exp2f(s2[ni][2] - mn2b);
                q3v = exp2f(s2[ni][3] - mn2b);
                su2a += q0v + q1v; su2b += q2v + q3v;
                h0 = __float2bfloat16(q0v); h1 = __float2bfloat16(q1v);
                h2 = __float2bfloat16(q2v); h3 = __float2bfloat16(q3v);
                p2h[j][2 * e]     = packbf(h0, h1);
                p2h[j][2 * e + 1] = packbf(h2, h3);
                p2l[j][2 * e]     = packbf(__float2bfloat16(q0v - __bfloat162float(h0)),
                                           __float2bfloat16(q1v - __bfloat162float(h1)));
                p2l[j][2 * e + 1] = packbf(__float2bfloat16(q2v - __bfloat162float(h2)),
                                           __float2bfloat16(q3v - __bfloat162float(h3)));
            }
        }
        su1a += __shfl_xor_sync(0xffffffffu, su1a, 1);
        su1a += __shfl_xor_sync(0xffffffffu, su1a, 2);
        su1b += __shfl_xor_sync(0xffffffffu, su1b, 1);
        su1b += __shfl_xor_sync(0xffffffffu, su1b, 2);
        su2a += __shfl_xor_sync(0xffffffffu, su2a, 1);
        su2a += __shfl_xor_sync(0xffffffffu, su2a, 2);
        su2b += __shfl_xor_sync(0xffffffffu, su2b, 1);
        su2b += __shfl_xor_sync(0xffffffffu, su2b, 2);
        if ((lane & 3) == 0) {
            ps[(half * 2 + 0) * 64 + r0]     = su1a;
            ps[(half * 2 + 0) * 64 + r0 + 8] = su1b;
            ps[(half * 2 + 1) * 64 + r0]     = su2a;
            ps[(half * 2 + 1) * 64 + r0 + 8] = su2b;
        }
        __syncthreads();
        {
            const int oh = 1 - half;
            l1a = l1a * sc1a + su1a + ps[(oh * 2 + 0) * 64 + r0];
            l1b = l1b * sc1b + su1b + ps[(oh * 2 + 0) * 64 + r0 + 8];
            l2a = l2a * sc2a + su2a + ps[(oh * 2 + 1) * 64 + r0];
            l2b = l2b * sc2b + su2b + ps[(oh * 2 + 1) * 64 + r0 + 8];
        }

        // ---- rescale O, then O += P V over this warp's key half ----
        #pragma unroll
        for (int nd = 0; nd < 8; nd++) {
            O1[nd][0] *= sc1a; O1[nd][1] *= sc1a; O1[nd][2] *= sc1b; O1[nd][3] *= sc1b;
            O2[nd][0] *= sc2a; O2[nd][1] *= sc2a; O2[nd][2] *= sc2b; O2[nd][3] *= sc2b;
        }
        #pragma unroll
        for (int j = 0; j < 2; j++) {
            #pragma unroll
            for (int nd = 0; nd < 8; nd++) {
                uint32_t voff = SW128((uint32_t)((kh + j * 16 + (lane & 15)) * 128 + nd * 16));
                uint32_t bvh[2], bvl[2];
                ldsm_x2t(bvh, sb + bufb + 32768u + voff);
                ldsm_x2t(bvl, sb + bufb + 40960u + voff);
                mma16816(O1[nd], p1h[j], bvh); mma16816(O1[nd], p1h[j], bvl); mma16816(O1[nd], p1l[j], bvh);
                mma16816(O2[nd], p2h[j], bvh); mma16816(O2[nd], p2h[j], bvl); mma16816(O2[nd], p2l[j], bvh);
            }
        }
    }
    __syncthreads();

    // ---- cross-half combine: G = O1/l1 - lam*O2/l2 (distributive) ----
    float* comb = (float*)(smem + ACMB);   // [64][66]
    const float lam = lam_p[0];
    const float i1a = 1.0f / l1a, i1b = 1.0f / l1b;
    const float i2a = lam  / l2a, i2b = lam  / l2b;
    if (half == 1) {
        #pragma unroll
        for (int nd = 0; nd < 8; nd++) {
            int cc = nd * 8 + (lane & 3) * 2;
            *(float2*)(comb + r0 * 66 + cc) =
                make_float2(O1[nd][0] * i1a - O2[nd][0] * i2a,
                            O1[nd][1] * i1a - O2[nd][1] * i2a);
            *(float2*)(comb + (r0 + 8) * 66 + cc) =
                make_float2(O1[nd][2] * i1b - O2[nd][2] * i2b,
                            O1[nd][3] * i1b - O2[nd][3] * i2b);
        }
    }
    __syncthreads();
    if (half == 0) {
        #pragma unroll
        for (int nd = 0; nd < 8; nd++) {
            int cc = nd * 8 + (lane & 3) * 2;
            float2 g0 = *(float2*)(comb + r0 * 66 + cc);
            float2 g1 = *(float2*)(comb + (r0 + 8) * 66 + cc);
            float2 v0 = make_float2(O1[nd][0] * i1a - O2[nd][0] * i2a + g0.x,
                                    O1[nd][1] * i1a - O2[nd][1] * i2a + g0.y);
            float2 v1 = make_float2(O1[nd][2] * i1b - O2[nd][2] * i2b + g1.x,
                                    O1[nd][3] * i1b - O2[nd][3] * i2b + g1.y);
            int s0 = q0 + r0, s1r = s0 + 8;
            *(float2*)(g_attn + (size_t)((b * Sc + s0)  * Hc + h) * Dc + cc) = v0;
            *(float2*)(g_attn + (size_t)((b * Sc + s1r) * Hc + h) * Dc + cc) = v1;
        }
    }
}

// ============================================================
// Group statistics (unchanged)
// ============================================================
__global__ __launch_bounds__(256)
void stats_kernel()
{
    const int b = blockIdx.x >> 3;
    const int j = blockIdx.x & 7;
    const int tid = threadIdx.x;
    double s = 0.0, sq = 0.0;
    const float* base = g_attn + (size_t)b*Sc*Hc*Dc + j*8;
    for (int t = tid; t < Sc*Hc; t += 256) {
        const float* p = base + (size_t)t * 64;
        #pragma unroll
        for (int i = 0; i < 8; i++) {
            float x = p[i];
            s  += (double)x;
            sq += (double)x * (double)x;
        }
    }
    __shared__ double ss[256], sqq[256];
    ss[tid] = s; sqq[tid] = sq;
    __syncthreads();
    for (int o = 128; o > 0; o >>= 1) {
        if (tid < o) { ss[tid] += ss[tid+o]; sqq[tid] += sqq[tid+o]; }
        __syncthreads();
    }
    if (tid == 0) {
        double mean = ss[0] / 65536.0;
        double var  = sqq[0] / 65536.0 - mean * mean;
        g_mean[blockIdx.x] = (float)mean;
        g_rstd[blockIdx.x] = (float)(1.0 / sqrt(var + 1e-3));
    }
}

// ============================================================
// Final elementwise (unchanged)
// ============================================================
__global__ __launch_bounds__(256)
void final_kernel(const float* __restrict__ gamma, const float* __restrict__ beta,
                  const float* __restrict__ li_p, float* __restrict__ out)
{
    const int idx = (blockIdx.x * 256 + threadIdx.x) * 4;
    const int d = idx & 63;
    const int h = (idx >> 6) & 7;
    const int s = (idx >> 9) & 1023;
    const int b = idx >> 19;
    const int j = d >> 3;
    const float mean = g_mean[b*8+j];
    const float rstd = g_rstd[b*8+j];
    const float li = 1.0f - li_p[0];
    float4 a  = *(const float4*)(g_attn + idx);
    float4 g  = *(const float4*)(g_gate + (size_t)((b*Hc+h)*Sc + s)*Dc + d);
    float4 gm = *(const float4*)(gamma + d);
    float4 bt = *(const float4*)(beta + d);
    float4 o;
    o.x = ((a.x-mean)*rstd*gm.x + bt.x) * li * (1.0f/(1.0f+__expf(-g.x)));
    o.y = ((a.y-mean)*rstd*gm.y + bt.y) * li * (1.0f/(1.0f+__expf(-g.y)));
    o.z = ((a.z-mean)*rstd*gm.z + bt.z) * li * (1.0f/(1.0f+__expf(-g.z)));
    o.w = ((a.w-mean)*rstd*gm.w + bt.w) * li * (1.0f/(1.0f+__expf(-g.w)));
    *(float4*)(out + idx) = o;
}

// ============================================================
extern "C" void kernel_launch(void* const* d_in, const int* in_sizes, int n_in,
                              void* d_out, int out_size)
{
    const float* query  = (const float*)d_in[0];
    const float* key    = (const float*)d_in[1];
    const float* values = (const float*)d_in[2];
    const float* Wq = (const float*)d_in[3];
    const float* bq = (const float*)d_in[4];
    const float* Wk = (const float*)d_in[5];
    const float* bk = (const float*)d_in[6];
    const float* Wv = (const float*)d_in[7];
    const float* bv = (const float*)d_in[8];
    const float* gamma = (const float*)d_in[9];
    const float* beta  = (const float*)d_in[10];
    const float* lam   = (const float*)d_in[11];
    const float* lambda_init = (const float*)d_in[12];
    float* out = (float*)d_out;

    cudaFuncSetAttribute(gemm_hmma, cudaFuncAttributeMaxDynamicSharedMemorySize, GEMM_SMEM);
    cudaFuncSetAttribute(attn_hmma, cudaFuncAttributeMaxDynamicSharedMemorySize, ATTN_SMEM);

    convA_all<<<12288, 256>>>(query, key, values);
    convW_all<<<dim3(16, 96), 256>>>(Wq, Wk, Wv);

    gemm_hmma<<<dim3(64, 12), 256, GEMM_SMEM>>>(0, 0,        bq, 192, 0);
    gemm_hmma<<<dim3(64,  8), 256, GEMM_SMEM>>>(1, 1536*512, bk, 128, 1);
    gemm_hmma<<<dim3(64,  4), 256, GEMM_SMEM>>>(2, 2560*512, bv,  64, 2);

    attn_hmma<<<dim3(16, 8, 8), 256, ATTN_SMEM>>>(lam);

    stats_kernel<<<64, 256>>>();
    final_kernel<<<NTOT/1024, 256>>>(gamma, beta, lambda_init, out);
}